// round 13
// baseline (speedup 1.0000x reference)
#include <cuda_runtime.h>
#include <cuda_fp16.h>
#include <math.h>

#define HID 128
#define NMAX 50048
#define EMAX 1600000

// ---------------- device scratch ----------------
__device__ float   g_h[NMAX * HID];       // fp32 h (residual + decoder)
__device__ __half  g_hh[NMAX * HID];      // fp16 h (GEMM input)
__device__ __half2 g_xlh[NMAX * 64];      // xl fp16 (gather payload)
__device__ __half2 g_xrh[NMAX * 64];      // xr fp16
__device__ float   g_gamma[NMAX * HID];
__device__ float   g_beta[NMAX * HID];
__device__ uint2   g_eah[EMAX];           // edge_attr fp16 x4, CSR-permuted
__device__ __half  g_Wh[4 * 256 * 128];   // [layer][n:256][k:128] fp16 weights
__device__ int     g_off[NMAX + 1];
__device__ int     g_cnt[NMAX];           // zero-init at load; re-zeroed by k_dec
__device__ int     g_csrc[EMAX];
__device__ int     g_viol[2];
__device__ int     g_maskmode;

__device__ __forceinline__ float gelu_f(float x) {
    return 0.5f * x * (1.0f + erff(x * 0.7071067811865476f));
}
__device__ __forceinline__ __half2 h2bits(unsigned u) { return *(__half2*)&u; }

// ---------------- CSR count + mask detect + weight fp16 conversion ----------------
__global__ void k_count(const int* ei, const int* m,
                        const float* __restrict__ Wl, const float* __restrict__ Wr,
                        int e, int n) {
    int i = blockIdx.x * blockDim.x + threadIdx.x;
    if (i < e) atomicAdd(&g_cnt[ei[e + i]], 1);
    int words = n >> 2;
    int lim = words < 8192 ? words : 8192;
    if (i < lim) {
        int v = m[i];
        if (v != 0 && v != 1) atomicOr(&g_viol[0], 1);
        if (v != 0 && v != 0x3F800000) atomicOr(&g_viol[1], 1);
    }
    if (i < 4 * 32768) {
        int l = i >> 15, rem = i & 32767;
        int nn = rem & 255, kk = rem >> 8;
        float v = (nn < 128) ? Wl[l * 16384 + kk * 128 + nn]
                             : Wr[l * 16384 + kk * 128 + nn - 128];
        g_Wh[(l << 15) + nn * 128 + kk] = __float2half_rn(v);
    }
}

// ---------------- merged: block 0 = scan, blocks 1.. = encoder+FiLM prep ----------------
__global__ void k_scan_prep(const float* __restrict__ x, const float* __restrict__ tmp,
                            const float* __restrict__ encW, const float* __restrict__ encB,
                            const float* __restrict__ encG, const float* __restrict__ encBe,
                            const float* __restrict__ fW1, const float* __restrict__ fb1,
                            const float* __restrict__ fW2, const float* __restrict__ fb2,
                            int n) {
    int tid = threadIdx.x;
    if (blockIdx.x == 0) {
        __shared__ int warpsum[32];
        int t = tid;
        int per = (n + 1023) >> 10;
        int i0 = t * per;
        int i1 = i0 + per; if (i1 > n) i1 = n; if (i0 > n) i0 = n;
        int local = 0;
        for (int i = i0; i < i1; i++) local += g_cnt[i];
        int lane = t & 31, warp = t >> 5;
        int v = local;
        #pragma unroll
        for (int o = 1; o < 32; o <<= 1) {
            int u = __shfl_up_sync(0xFFFFFFFFu, v, o);
            if (lane >= o) v += u;
        }
        if (lane == 31) warpsum[warp] = v;
        __syncthreads();
        if (warp == 0) {
            int w = warpsum[lane];
            #pragma unroll
            for (int o = 1; o < 32; o <<= 1) {
                int u = __shfl_up_sync(0xFFFFFFFFu, w, o);
                if (lane >= o) w += u;
            }
            warpsum[lane] = w;
        }
        __syncthreads();
        int excl = v - local + (warp ? warpsum[warp - 1] : 0);
        int run = excl;
        for (int i = i0; i < i1; i++) {
            int c = g_cnt[i];
            g_off[i] = run;
            g_cnt[i] = run;
            run += c;
        }
        if (t == 1023) g_off[n] = run;
        if (t == 0) g_maskmode = (g_viol[0] == 0) ? 0 : ((g_viol[1] == 0) ? 1 : 2);
        return;
    }
    extern __shared__ float sm[];
    float* sEncW = sm;            // 768
    float* sW1   = sm + 768;      // 64
    float* sB1   = sm + 832;      // 64
    float* sB2   = sm + 896;      // 256
    float* sW2   = sm + 1152;     // 16384
    float* sT1   = sm + 17536;    // 2048 (32 warps x 64)
    for (int i = tid; i < 768; i += blockDim.x) sEncW[i] = encW[i];
    for (int i = tid; i < 64; i += blockDim.x) { sW1[i] = fW1[i]; sB1[i] = fb1[i]; }
    for (int i = tid; i < 256; i += blockDim.x) sB2[i] = fb2[i];
    for (int i = tid; i < 4096; i += blockDim.x)
        ((float4*)sW2)[i] = ((const float4*)fW2)[i];
    __syncthreads();
    int warp = tid >> 5, lane = tid & 31;
    int nb = gridDim.x - 1, pb = blockIdx.x - 1;
    for (int i = pb * 32 + warp; i < n; i += nb * 32) {
        float xv[6];
        #pragma unroll
        for (int j = 0; j < 6; j++) xv[j] = x[i * 6 + j];
        float y[4];
        #pragma unroll
        for (int h = 0; h < 4; h++) {
            int k = h * 32 + lane;
            float a = encB[k];
            #pragma unroll
            for (int j = 0; j < 6; j++) a += xv[j] * sEncW[j * 128 + k];
            y[h] = a;
        }
        float s1 = y[0] + y[1] + y[2] + y[3];
        float s2 = y[0]*y[0] + y[1]*y[1] + y[2]*y[2] + y[3]*y[3];
        #pragma unroll
        for (int o = 16; o > 0; o >>= 1) {
            s1 += __shfl_xor_sync(0xFFFFFFFFu, s1, o);
            s2 += __shfl_xor_sync(0xFFFFFFFFu, s2, o);
        }
        float mean = s1 * (1.0f / 128.0f);
        float var  = s2 * (1.0f / 128.0f) - mean * mean;
        float inv  = rsqrtf(var + 1e-5f);
        #pragma unroll
        for (int h = 0; h < 4; h++) {
            int k = h * 32 + lane;
            float v = (y[h] - mean) * inv * encG[k] + encBe[k];
            float g = gelu_f(v);
            g_h[i * 128 + k]  = g;
            g_hh[i * 128 + k] = __float2half_rn(g);
        }
        float tm = tmp[i];
        #pragma unroll
        for (int c = 0; c < 2; c++) {
            int j = lane + 32 * c;
            sT1[warp * 64 + j] = gelu_f(tm * sW1[j] + sB1[j]);
        }
        __syncwarp();
        float f[8];
        #pragma unroll
        for (int c = 0; c < 8; c++) f[c] = sB2[lane + 32 * c];
        for (int j = 0; j < 64; j++) {
            float t = sT1[warp * 64 + j];
            #pragma unroll
            for (int c = 0; c < 8; c++) f[c] += t * sW2[j * 256 + lane + 32 * c];
        }
        #pragma unroll
        for (int c = 0; c < 4; c++) {
            g_gamma[i * 128 + lane + 32 * c] = f[c];
            g_beta[i * 128 + lane + 32 * c]  = f[c + 4];
        }
        __syncwarp();
    }
}

// ---------------- tensor-core half-GEMM body ----------------
// block computes 128 rows x 128 outputs; which==0 -> Wl -> g_xlh, which==1 -> Wr -> g_xrh
#define AST 136   // padded k-stride (halfs)
__device__ __forceinline__ void gemm_body(
    const __half* __restrict__ Wh, const float* __restrict__ bias,
    int n, int row0, int which, __half* smh, int tid) {
    __half* As = smh;               // 128 x 136
    __half* Bs = smh + 128 * AST;   // 128 x 136

    for (int idx = tid; idx < 2048; idx += 512) {
        int row = idx >> 4, c8 = idx & 15;
        int gr = row0 + row;
        uint4 v = make_uint4(0, 0, 0, 0);
        if (gr < n) v = ((const uint4*)g_hh)[gr * 16 + c8];
        *(uint4*)&As[row * AST + c8 * 8] = v;
    }
    const __half* Wsel = Wh + which * 16384;
    for (int idx = tid; idx < 2048; idx += 512) {
        int nn = idx >> 4, c8 = idx & 15;
        uint4 v = ((const uint4*)(Wsel + nn * 128))[c8];
        *(uint4*)&Bs[nn * AST + c8 * 8] = v;
    }
    __syncthreads();

    int warp = tid >> 5, lane = tid & 31;
    int mi = warp & 3, ni = warp >> 2;
    int gid = lane >> 2, tig = lane & 3;

    float d[2][4][4];
    #pragma unroll
    for (int tm = 0; tm < 2; tm++)
        #pragma unroll
        for (int tn = 0; tn < 4; tn++)
            #pragma unroll
            for (int q = 0; q < 4; q++) d[tm][tn][q] = 0.f;

    #pragma unroll
    for (int ks = 0; ks < 8; ks++) {
        int k0 = ks * 16;
        unsigned a[2][4];
        #pragma unroll
        for (int tm = 0; tm < 2; tm++) {
            int r = mi * 32 + tm * 16 + gid;
            a[tm][0] = *(const unsigned*)&As[r * AST + k0 + tig * 2];
            a[tm][1] = *(const unsigned*)&As[(r + 8) * AST + k0 + tig * 2];
            a[tm][2] = *(const unsigned*)&As[r * AST + k0 + tig * 2 + 8];
            a[tm][3] = *(const unsigned*)&As[(r + 8) * AST + k0 + tig * 2 + 8];
        }
        unsigned b[4][2];
        #pragma unroll
        for (int tn = 0; tn < 4; tn++) {
            int nn = ni * 32 + tn * 8 + gid;
            b[tn][0] = *(const unsigned*)&Bs[nn * AST + k0 + tig * 2];
            b[tn][1] = *(const unsigned*)&Bs[nn * AST + k0 + tig * 2 + 8];
        }
        #pragma unroll
        for (int tm = 0; tm < 2; tm++)
            #pragma unroll
            for (int tn = 0; tn < 4; tn++) {
                asm volatile(
                    "mma.sync.aligned.m16n8k16.row.col.f32.f16.f16.f32 "
                    "{%0,%1,%2,%3}, {%4,%5,%6,%7}, {%8,%9}, {%0,%1,%2,%3};\n"
                    : "+f"(d[tm][tn][0]), "+f"(d[tm][tn][1]),
                      "+f"(d[tm][tn][2]), "+f"(d[tm][tn][3])
                    : "r"(a[tm][0]), "r"(a[tm][1]), "r"(a[tm][2]), "r"(a[tm][3]),
                      "r"(b[tn][0]), "r"(b[tn][1]));
            }
    }

    __half2* dst = which ? g_xrh : g_xlh;
    #pragma unroll
    for (int tn = 0; tn < 4; tn++) {
        int nglob = ni * 32 + tn * 8 + tig * 2;   // 0..127
        float b0 = bias[nglob], b1 = bias[nglob + 1];
        #pragma unroll
        for (int tm = 0; tm < 2; tm++) {
            int r0 = row0 + mi * 32 + tm * 16 + gid;
            int r1 = r0 + 8;
            float v0 = d[tm][tn][0] + b0, v1 = d[tm][tn][1] + b1;
            float v2 = d[tm][tn][2] + b0, v3 = d[tm][tn][3] + b1;
            int c = nglob >> 1;
            if (r0 < n) dst[r0 * 64 + c] = __floats2half2_rn(v0, v1);
            if (r1 < n) dst[r1 * 64 + c] = __floats2half2_rn(v2, v3);
        }
    }
}

__global__ void __launch_bounds__(512, 2)
k_gemm(const __half* __restrict__ Wh, const float* __restrict__ blv,
       const float* __restrict__ brv, int n) {
    extern __shared__ __half smh[];
    int which = blockIdx.x & 1;
    gemm_body(Wh, which ? brv : blv, n, (blockIdx.x >> 1) * 128, which,
              smh, threadIdx.x);
}

// merged: gemm blocks [0, gB) + scatter blocks [gB, ...)
__global__ void __launch_bounds__(512, 2)
k_scatter_gemm(const __half* __restrict__ Wh, const float* __restrict__ blv,
               const float* __restrict__ brv,
               const int* ei, const float4* __restrict__ ea, int e, int n, int gB) {
    extern __shared__ __half smh[];
    if ((int)blockIdx.x < gB) {
        int which = blockIdx.x & 1;
        gemm_body(Wh, which ? brv : blv, n, (blockIdx.x >> 1) * 128, which,
                  smh, threadIdx.x);
        return;
    }
    int base = (blockIdx.x - gB) * 1024 + threadIdx.x;
    #pragma unroll
    for (int k = 0; k < 2; k++) {
        int idx = base + k * 512;
        if (idx < e) {
            int s = ei[idx], d = ei[e + idx];
            int pos = atomicAdd(&g_cnt[d], 1);
            g_csrc[pos] = s;
            float4 a = ea[idx];
            __half2 h0 = __floats2half2_rn(a.x, a.y);
            __half2 h1 = __floats2half2_rn(a.z, a.w);
            g_eah[pos] = make_uint2(*(unsigned*)&h0, *(unsigned*)&h1);
        }
    }
}

// ---- fused edge+softmax+aggregate+FiLM+LN+GELU+residual ----
// R11 structure: one warp/node, lane owns 4 channels, MLP=4; reg cap for occupancy
__global__ void __launch_bounds__(256, 6)
k_node(const float* __restrict__ We, const float* __restrict__ att,
       const float* __restrict__ cb, const float* __restrict__ lng,
       const float* __restrict__ lnb, int n) {
    int tid = threadIdx.x;
    int warp = tid >> 5, lane = tid & 31;
    int i = blockIdx.x * 8 + warp;
    if (i >= n) return;

    float4 wf0 = ((const float4*)We)[lane];
    float4 wf1 = ((const float4*)We)[32 + lane];
    float4 wf2 = ((const float4*)We)[64 + lane];
    float4 wf3 = ((const float4*)We)[96 + lane];
    __half2 w0a = __floats2half2_rn(wf0.x, wf0.y), w0b = __floats2half2_rn(wf0.z, wf0.w);
    __half2 w1a = __floats2half2_rn(wf1.x, wf1.y), w1b = __floats2half2_rn(wf1.z, wf1.w);
    __half2 w2a = __floats2half2_rn(wf2.x, wf2.y), w2b = __floats2half2_rn(wf2.z, wf2.w);
    __half2 w3a = __floats2half2_rn(wf3.x, wf3.y), w3b = __floats2half2_rn(wf3.z, wf3.w);
    float4 atf = ((const float4*)att)[lane];
    __half2 at01 = __floats2half2_rn(atf.x, atf.y), at23 = __floats2half2_rn(atf.z, atf.w);
    uint2 xrr = ((const uint2*)g_xrh)[i * 32 + lane];
    __half2 xr01 = h2bits(xrr.x), xr23 = h2bits(xrr.y);
    const __half2 c02 = __float2half2_rn(0.2f);

    int beg = g_off[i], end = g_off[i + 1];
    float sme = 0.f;
    float4 acc = make_float4(0.f, 0.f, 0.f, 0.f);
    const uint2* xlh = (const uint2*)g_xlh;

    for (int j = beg; j < end; j += 4) {
        int c = end - j;
        int s0 = g_csrc[j];
        int s1 = (c > 1) ? g_csrc[j + 1] : s0;
        int s2 = (c > 2) ? g_csrc[j + 2] : s0;
        int s3 = (c > 3) ? g_csrc[j + 3] : s0;
        uint2 e0 = g_eah[j];
        uint2 e1 = (c > 1) ? g_eah[j + 1] : e0;
        uint2 e2 = (c > 2) ? g_eah[j + 2] : e0;
        uint2 e3 = (c > 3) ? g_eah[j + 3] : e0;
        uint2 r0 = xlh[s0 * 32 + lane];
        uint2 r1 = xlh[s1 * 32 + lane];
        uint2 r2 = xlh[s2 * 32 + lane];
        uint2 r3 = xlh[s3 * 32 + lane];

        float2 xa0, xb0, xa1, xb1, xa2, xb2, xa3, xb3;
        float p0, p1, p2, p3;
        #define EDGE_H2(rr, ed, xa, xb, pp)                                      \
        {                                                                        \
            __half2 xl01 = h2bits(rr.x), xl23 = h2bits(rr.y);                    \
            __half2 ex = h2bits(ed.x), ey = h2bits(ed.y);                        \
            __half2 b0 = __low2half2(ex), b1 = __high2half2(ex);                 \
            __half2 b2 = __low2half2(ey), b3 = __high2half2(ey);                 \
            __half2 m01 = __hadd2(xl01, xr01);                                   \
            m01 = __hfma2(b0, w0a, m01); m01 = __hfma2(b1, w1a, m01);            \
            m01 = __hfma2(b2, w2a, m01); m01 = __hfma2(b3, w3a, m01);            \
            __half2 m23 = __hadd2(xl23, xr23);                                   \
            m23 = __hfma2(b0, w0b, m23); m23 = __hfma2(b1, w1b, m23);            \
            m23 = __hfma2(b2, w2b, m23); m23 = __hfma2(b3, w3b, m23);            \
            m01 = __hmax2(m01, __hmul2(m01, c02));                               \
            m23 = __hmax2(m23, __hmul2(m23, c02));                               \
            __half2 pr = __hmul2(m01, at01);                                     \
            pr = __hfma2(m23, at23, pr);                                         \
            float2 pf = __half22float2(pr);                                      \
            pp = pf.x + pf.y;                                                    \
            xa = __half22float2(xl01);                                           \
            xb = __half22float2(xl23);                                           \
        }
        EDGE_H2(r0, e0, xa0, xb0, p0)
        EDGE_H2(r1, e1, xa1, xb1, p1)
        EDGE_H2(r2, e2, xa2, xb2, p2)
        EDGE_H2(r3, e3, xa3, xb3, p3)
        #undef EDGE_H2

        #pragma unroll
        for (int o = 1; o < 8; o <<= 1) {
            p0 += __shfl_xor_sync(0xFFFFFFFFu, p0, o);
            p1 += __shfl_xor_sync(0xFFFFFFFFu, p1, o);
            p2 += __shfl_xor_sync(0xFFFFFFFFu, p2, o);
            p3 += __shfl_xor_sync(0xFFFFFFFFu, p3, o);
        }
        float w0 = __expf(p0);
        float w1 = (c > 1) ? __expf(p1) : 0.f;
        float w2 = (c > 2) ? __expf(p2) : 0.f;
        float w3 = (c > 3) ? __expf(p3) : 0.f;
        sme += (w0 + w1) + (w2 + w3);
        acc.x += w0*xa0.x + w1*xa1.x + w2*xa2.x + w3*xa3.x;
        acc.y += w0*xa0.y + w1*xa1.y + w2*xa2.y + w3*xa3.y;
        acc.z += w0*xb0.x + w1*xb1.x + w2*xb2.x + w3*xb3.x;
        acc.w += w0*xb0.y + w1*xb1.y + w2*xb2.y + w3*xb3.y;
    }

    float inv = 1.0f / (sme + 1e-16f);
    float4 cb4 = ((const float4*)cb)[lane];
    float4 ga  = ((const float4*)g_gamma)[i * 32 + lane];
    float4 be  = ((const float4*)g_beta)[i * 32 + lane];
    float y0 = ga.x * (acc.x * inv + cb4.x) + be.x;
    float y1 = ga.y * (acc.y * inv + cb4.y) + be.y;
    float y2 = ga.z * (acc.z * inv + cb4.z) + be.z;
    float y3 = ga.w * (acc.w * inv + cb4.w) + be.w;
    float s1 = y0 + y1 + y2 + y3;
    float s2 = y0*y0 + y1*y1 + y2*y2 + y3*y3;
    #pragma unroll
    for (int o = 16; o > 0; o >>= 1) {
        s1 += __shfl_xor_sync(0xFFFFFFFFu, s1, o);
        s2 += __shfl_xor_sync(0xFFFFFFFFu, s2, o);
    }
    float mean = s1 * (1.0f / 128.0f);
    float var  = s2 * (1.0f / 128.0f) - mean * mean;
    float ivs  = rsqrtf(var + 1e-5f);
    float4 g4 = ((const float4*)lng)[lane];
    float4 b4 = ((const float4*)lnb)[lane];
    float4 ho = ((const float4*)g_h)[i * 32 + lane];
    float4 out;
    out.x = gelu_f((y0 - mean) * ivs * g4.x + b4.x) + ho.x;
    out.y = gelu_f((y1 - mean) * ivs * g4.y + b4.y) + ho.y;
    out.z = gelu_f((y2 - mean) * ivs * g4.z + b4.z) + ho.z;
    out.w = gelu_f((y3 - mean) * ivs * g4.w + b4.w) + ho.w;
    ((float4*)g_h)[i * 32 + lane] = out;
    __half2 o0 = __floats2half2_rn(out.x, out.y);
    __half2 o1 = __floats2half2_rn(out.z, out.w);
    uint2 pk;
    pk.x = *(unsigned*)&o0;
    pk.y = *(unsigned*)&o1;
    ((uint2*)g_hh)[i * 32 + lane] = pk;
}

// ---------------- decoder + mask + output (+ reset counters) ----------------
__global__ void k_dec(const float* __restrict__ W1, const float* __restrict__ b1,
                      const float* __restrict__ W2, const float* __restrict__ b2,
                      const float* __restrict__ x, const void* __restrict__ mask,
                      float* __restrict__ out, int n, int out_size) {
    __shared__ float sW1[8192];
    __shared__ float sW2[128];
    __shared__ float sb1v[64];
    __shared__ float sb2v[2];
    __shared__ float sH[8][128];
    int tid = threadIdx.x;
    int gid = blockIdx.x * blockDim.x + tid;
    if (gid < n) g_cnt[gid] = 0;
    if (gid < 2) g_viol[gid] = 0;
    for (int i = tid; i < 8192; i += 256) sW1[i] = W1[i];
    if (tid < 128) sW2[tid] = W2[tid];
    if (tid < 64) sb1v[tid] = b1[tid];
    if (tid < 2) sb2v[tid] = b2[tid];
    __syncthreads();
    int warp = tid >> 5, lane = tid & 31;
    int mode = g_maskmode;
    for (int i = blockIdx.x * 8 + warp; i < n; i += gridDim.x * 8) {
        #pragma unroll
        for (int h = 0; h < 4; h++) sH[warp][h * 32 + lane] = g_h[i * 128 + h * 32 + lane];
        __syncwarp();
        float a0 = sb1v[lane], a1 = sb1v[lane + 32];
        for (int k = 0; k < 128; k++) {
            float hv = sH[warp][k];
            a0 += hv * sW1[k * 64 + lane];
            a1 += hv * sW1[k * 64 + lane + 32];
        }
        float t0 = gelu_f(a0), t1 = gelu_f(a1);
        float d0 = t0 * sW2[lane * 2]     + t1 * sW2[(lane + 32) * 2];
        float d1 = t0 * sW2[lane * 2 + 1] + t1 * sW2[(lane + 32) * 2 + 1];
        #pragma unroll
        for (int o = 16; o > 0; o >>= 1) {
            d0 += __shfl_xor_sync(0xFFFFFFFFu, d0, o);
            d1 += __shfl_xor_sync(0xFFFFFFFFu, d1, o);
        }
        if (lane == 0) {
            d0 += sb2v[0]; d1 += sb2v[1];
            int fixed;
            if (mode == 0)      fixed = ((const int*)mask)[i] != 0;
            else if (mode == 1) fixed = ((const float*)mask)[i] != 0.f;
            else                fixed = ((const unsigned char*)mask)[i] != 0;
            if (fixed) { d0 = 0.f; d1 = 0.f; }
            out[i * 2]     = x[i * 6]     + d0;
            out[i * 2 + 1] = x[i * 6 + 1] + d1;
            if (out_size >= 4 * n) {
                out[2 * n + i * 2]     = d0;
                out[2 * n + i * 2 + 1] = d1;
            }
        }
        __syncwarp();
    }
}

// ---------------- launch ----------------
extern "C" void kernel_launch(void* const* d_in, const int* in_sizes, int n_in,
                              void* d_out, int out_size) {
    const float* x    = (const float*)d_in[0];
    const int*   ei   = (const int*)d_in[1];
    const float* ea   = (const float*)d_in[2];
    const float* tmp  = (const float*)d_in[3];
    const void*  mask = d_in[4];
    const float* encW = (const float*)d_in[5];
    const float* encB = (const float*)d_in[6];
    const float* encG = (const float*)d_in[7];
    const float* encBe= (const float*)d_in[8];
    const float* fW1  = (const float*)d_in[9];
    const float* fb1  = (const float*)d_in[10];
    const float* fW2  = (const float*)d_in[11];
    const float* fb2  = (const float*)d_in[12];
    const float* Wl   = (const float*)d_in[13];
    const float* bl   = (const float*)d_in[14];
    const float* Wr   = (const float*)d_in[15];
    const float* br   = (const float*)d_in[16];
    const float* We   = (const float*)d_in[17];
    const float* att  = (const float*)d_in[18];
    const float* cb   = (const float*)d_in[19];
    const float* lng  = (const float*)d_in[20];
    const float* lnb  = (const float*)d_in[21];
    const float* dW1  = (const float*)d_in[22];
    const float* db1  = (const float*)d_in[23];
    const float* dW2  = (const float*)d_in[24];
    const float* db2  = (const float*)d_in[25];
    float* out = (float*)d_out;

    int n = in_sizes[0] / 6;
    int e = in_sizes[2] / 4;

    const int gemm_smem = 256 * AST * 2;                // 69632
    const int prep_smem = (17536 + 2048) * 4;           // 78336
    cudaFuncSetAttribute(k_scan_prep, cudaFuncAttributeMaxDynamicSharedMemorySize, prep_smem);
    cudaFuncSetAttribute(k_gemm, cudaFuncAttributeMaxDynamicSharedMemorySize, gemm_smem);
    cudaFuncSetAttribute(k_scatter_gemm, cudaFuncAttributeMaxDynamicSharedMemorySize, gemm_smem);

    int gB = 2 * ((n + 127) / 128);     // 2 half-gemm blocks per 128-row tile
    int sB = (e + 1023) / 1024;

    __half* Wh = nullptr;
    cudaGetSymbolAddress((void**)&Wh, g_Wh);

    // launches: count(0), scan_prep(1), scatter_gemm0(2), node0(3) <- profiled
    k_count<<<(e + 255) / 256, 256>>>(ei, (const int*)mask, Wl, Wr, e, n);
    k_scan_prep<<<201, 1024, prep_smem>>>(x, tmp, encW, encB, encG, encBe,
                                          fW1, fb1, fW2, fb2, n);
    k_scatter_gemm<<<gB + sB, 512, gemm_smem>>>(Wh, bl, br,
                                                ei, (const float4*)ea, e, n, gB);
    k_node<<<(n + 7) / 8, 256>>>(We, att, cb, lng, lnb, n);

    for (int l = 1; l < 4; l++) {
        k_gemm<<<gB, 512, gemm_smem>>>(Wh + l * 32768, bl + l * 128,
                                       br + l * 128, n);
        k_node<<<(n + 7) / 8, 256>>>(We + l * 512, att + l * 128,
                                     cb + l * 128, lng + l * 128, lnb + l * 128, n);
    }

    k_dec<<<1536, 256>>>(dW1, db1, dW2, db2, x, mask, out, n, out_size);
}

// round 14
// speedup vs baseline: 1.0377x; 1.0377x over previous
#include <cuda_runtime.h>
#include <cuda_fp16.h>
#include <math.h>

#define HID 128
#define NMAX 50048
#define EMAX 1600000

// ---------------- device scratch ----------------
__device__ float   g_h[NMAX * HID];       // fp32 h (residual + decoder)
__device__ __half  g_hh[NMAX * HID];      // fp16 h (GEMM input)
__device__ __half2 g_xlh[NMAX * 64];      // xl fp16 (gather payload)
__device__ __half2 g_xrh[NMAX * 64];      // xr fp16
__device__ float   g_gamma[NMAX * HID];
__device__ float   g_beta[NMAX * HID];
__device__ uint2   g_eah[EMAX + 4];       // edge_attr fp16 x4, CSR-permuted (+4 pad, never written)
__device__ __half  g_Wh[4 * 256 * 128];   // [layer][n:256][k:128] fp16 weights
__device__ int     g_off[NMAX + 1];
__device__ int     g_cnt[NMAX];           // zero-init at load; re-zeroed by k_dec
__device__ int     g_csrc[EMAX + 4];      // +4 pad slots stay zero forever
__device__ int     g_viol[2];
__device__ int     g_maskmode;

__device__ __forceinline__ float gelu_f(float x) {
    return 0.5f * x * (1.0f + erff(x * 0.7071067811865476f));
}
__device__ __forceinline__ __half2 h2bits(unsigned u) { return *(__half2*)&u; }

// ---------------- CSR count + mask detect + weight fp16 conversion ----------------
__global__ void k_count(const int* ei, const int* m,
                        const float* __restrict__ Wl, const float* __restrict__ Wr,
                        int e, int n) {
    int i = blockIdx.x * blockDim.x + threadIdx.x;
    if (i < e) atomicAdd(&g_cnt[ei[e + i]], 1);
    int words = n >> 2;
    int lim = words < 8192 ? words : 8192;
    if (i < lim) {
        int v = m[i];
        if (v != 0 && v != 1) atomicOr(&g_viol[0], 1);
        if (v != 0 && v != 0x3F800000) atomicOr(&g_viol[1], 1);
    }
    if (i < 4 * 32768) {
        int l = i >> 15, rem = i & 32767;
        int nn = rem & 255, kk = rem >> 8;
        float v = (nn < 128) ? Wl[l * 16384 + kk * 128 + nn]
                             : Wr[l * 16384 + kk * 128 + nn - 128];
        g_Wh[(l << 15) + nn * 128 + kk] = __float2half_rn(v);
    }
}

// ---------------- merged: block 0 = scan, blocks 1.. = encoder+FiLM prep ----------------
__global__ void k_scan_prep(const float* __restrict__ x, const float* __restrict__ tmp,
                            const float* __restrict__ encW, const float* __restrict__ encB,
                            const float* __restrict__ encG, const float* __restrict__ encBe,
                            const float* __restrict__ fW1, const float* __restrict__ fb1,
                            const float* __restrict__ fW2, const float* __restrict__ fb2,
                            int n) {
    int tid = threadIdx.x;
    if (blockIdx.x == 0) {
        __shared__ int warpsum[32];
        int t = tid;
        int per = (n + 1023) >> 10;
        int i0 = t * per;
        int i1 = i0 + per; if (i1 > n) i1 = n; if (i0 > n) i0 = n;
        int local = 0;
        for (int i = i0; i < i1; i++) local += g_cnt[i];
        int lane = t & 31, warp = t >> 5;
        int v = local;
        #pragma unroll
        for (int o = 1; o < 32; o <<= 1) {
            int u = __shfl_up_sync(0xFFFFFFFFu, v, o);
            if (lane >= o) v += u;
        }
        if (lane == 31) warpsum[warp] = v;
        __syncthreads();
        if (warp == 0) {
            int w = warpsum[lane];
            #pragma unroll
            for (int o = 1; o < 32; o <<= 1) {
                int u = __shfl_up_sync(0xFFFFFFFFu, w, o);
                if (lane >= o) w += u;
            }
            warpsum[lane] = w;
        }
        __syncthreads();
        int excl = v - local + (warp ? warpsum[warp - 1] : 0);
        int run = excl;
        for (int i = i0; i < i1; i++) {
            int c = g_cnt[i];
            g_off[i] = run;
            g_cnt[i] = run;
            run += c;
        }
        if (t == 1023) g_off[n] = run;
        if (t == 0) g_maskmode = (g_viol[0] == 0) ? 0 : ((g_viol[1] == 0) ? 1 : 2);
        return;
    }
    extern __shared__ float sm[];
    float* sEncW = sm;            // 768
    float* sW1   = sm + 768;      // 64
    float* sB1   = sm + 832;      // 64
    float* sB2   = sm + 896;      // 256
    float* sW2   = sm + 1152;     // 16384
    float* sT1   = sm + 17536;    // 2048 (32 warps x 64)
    for (int i = tid; i < 768; i += blockDim.x) sEncW[i] = encW[i];
    for (int i = tid; i < 64; i += blockDim.x) { sW1[i] = fW1[i]; sB1[i] = fb1[i]; }
    for (int i = tid; i < 256; i += blockDim.x) sB2[i] = fb2[i];
    for (int i = tid; i < 4096; i += blockDim.x)
        ((float4*)sW2)[i] = ((const float4*)fW2)[i];
    __syncthreads();
    int warp = tid >> 5, lane = tid & 31;
    int nb = gridDim.x - 1, pb = blockIdx.x - 1;
    for (int i = pb * 32 + warp; i < n; i += nb * 32) {
        float xv[6];
        #pragma unroll
        for (int j = 0; j < 6; j++) xv[j] = x[i * 6 + j];
        float y[4];
        #pragma unroll
        for (int h = 0; h < 4; h++) {
            int k = h * 32 + lane;
            float a = encB[k];
            #pragma unroll
            for (int j = 0; j < 6; j++) a += xv[j] * sEncW[j * 128 + k];
            y[h] = a;
        }
        float s1 = y[0] + y[1] + y[2] + y[3];
        float s2 = y[0]*y[0] + y[1]*y[1] + y[2]*y[2] + y[3]*y[3];
        #pragma unroll
        for (int o = 16; o > 0; o >>= 1) {
            s1 += __shfl_xor_sync(0xFFFFFFFFu, s1, o);
            s2 += __shfl_xor_sync(0xFFFFFFFFu, s2, o);
        }
        float mean = s1 * (1.0f / 128.0f);
        float var  = s2 * (1.0f / 128.0f) - mean * mean;
        float inv  = rsqrtf(var + 1e-5f);
        #pragma unroll
        for (int h = 0; h < 4; h++) {
            int k = h * 32 + lane;
            float v = (y[h] - mean) * inv * encG[k] + encBe[k];
            float g = gelu_f(v);
            g_h[i * 128 + k]  = g;
            g_hh[i * 128 + k] = __float2half_rn(g);
        }
        float tm = tmp[i];
        #pragma unroll
        for (int c = 0; c < 2; c++) {
            int j = lane + 32 * c;
            sT1[warp * 64 + j] = gelu_f(tm * sW1[j] + sB1[j]);
        }
        __syncwarp();
        float f[8];
        #pragma unroll
        for (int c = 0; c < 8; c++) f[c] = sB2[lane + 32 * c];
        for (int j = 0; j < 64; j++) {
            float t = sT1[warp * 64 + j];
            #pragma unroll
            for (int c = 0; c < 8; c++) f[c] += t * sW2[j * 256 + lane + 32 * c];
        }
        #pragma unroll
        for (int c = 0; c < 4; c++) {
            g_gamma[i * 128 + lane + 32 * c] = f[c];
            g_beta[i * 128 + lane + 32 * c]  = f[c + 4];
        }
        __syncwarp();
    }
}

// ---------------- tensor-core half-GEMM body ----------------
// block computes 128 rows x 128 outputs; which==0 -> Wl -> g_xlh, which==1 -> Wr -> g_xrh
#define AST 136   // padded k-stride (halfs)
__device__ __forceinline__ void gemm_body(
    const __half* __restrict__ Wh, const float* __restrict__ bias,
    int n, int row0, int which, __half* smh, int tid) {
    __half* As = smh;               // 128 x 136
    __half* Bs = smh + 128 * AST;   // 128 x 136

    for (int idx = tid; idx < 2048; idx += 512) {
        int row = idx >> 4, c8 = idx & 15;
        int gr = row0 + row;
        uint4 v = make_uint4(0, 0, 0, 0);
        if (gr < n) v = ((const uint4*)g_hh)[gr * 16 + c8];
        *(uint4*)&As[row * AST + c8 * 8] = v;
    }
    const __half* Wsel = Wh + which * 16384;
    for (int idx = tid; idx < 2048; idx += 512) {
        int nn = idx >> 4, c8 = idx & 15;
        uint4 v = ((const uint4*)(Wsel + nn * 128))[c8];
        *(uint4*)&Bs[nn * AST + c8 * 8] = v;
    }
    __syncthreads();

    int warp = tid >> 5, lane = tid & 31;
    int mi = warp & 3, ni = warp >> 2;
    int gid = lane >> 2, tig = lane & 3;

    float d[2][4][4];
    #pragma unroll
    for (int tm = 0; tm < 2; tm++)
        #pragma unroll
        for (int tn = 0; tn < 4; tn++)
            #pragma unroll
            for (int q = 0; q < 4; q++) d[tm][tn][q] = 0.f;

    #pragma unroll
    for (int ks = 0; ks < 8; ks++) {
        int k0 = ks * 16;
        unsigned a[2][4];
        #pragma unroll
        for (int tm = 0; tm < 2; tm++) {
            int r = mi * 32 + tm * 16 + gid;
            a[tm][0] = *(const unsigned*)&As[r * AST + k0 + tig * 2];
            a[tm][1] = *(const unsigned*)&As[(r + 8) * AST + k0 + tig * 2];
            a[tm][2] = *(const unsigned*)&As[r * AST + k0 + tig * 2 + 8];
            a[tm][3] = *(const unsigned*)&As[(r + 8) * AST + k0 + tig * 2 + 8];
        }
        unsigned b[4][2];
        #pragma unroll
        for (int tn = 0; tn < 4; tn++) {
            int nn = ni * 32 + tn * 8 + gid;
            b[tn][0] = *(const unsigned*)&Bs[nn * AST + k0 + tig * 2];
            b[tn][1] = *(const unsigned*)&Bs[nn * AST + k0 + tig * 2 + 8];
        }
        #pragma unroll
        for (int tm = 0; tm < 2; tm++)
            #pragma unroll
            for (int tn = 0; tn < 4; tn++) {
                asm volatile(
                    "mma.sync.aligned.m16n8k16.row.col.f32.f16.f16.f32 "
                    "{%0,%1,%2,%3}, {%4,%5,%6,%7}, {%8,%9}, {%0,%1,%2,%3};\n"
                    : "+f"(d[tm][tn][0]), "+f"(d[tm][tn][1]),
                      "+f"(d[tm][tn][2]), "+f"(d[tm][tn][3])
                    : "r"(a[tm][0]), "r"(a[tm][1]), "r"(a[tm][2]), "r"(a[tm][3]),
                      "r"(b[tn][0]), "r"(b[tn][1]));
            }
    }

    __half2* dst = which ? g_xrh : g_xlh;
    #pragma unroll
    for (int tn = 0; tn < 4; tn++) {
        int nglob = ni * 32 + tn * 8 + tig * 2;   // 0..127
        float b0 = bias[nglob], b1 = bias[nglob + 1];
        #pragma unroll
        for (int tm = 0; tm < 2; tm++) {
            int r0 = row0 + mi * 32 + tm * 16 + gid;
            int r1 = r0 + 8;
            float v0 = d[tm][tn][0] + b0, v1 = d[tm][tn][1] + b1;
            float v2 = d[tm][tn][2] + b0, v3 = d[tm][tn][3] + b1;
            int c = nglob >> 1;
            if (r0 < n) dst[r0 * 64 + c] = __floats2half2_rn(v0, v1);
            if (r1 < n) dst[r1 * 64 + c] = __floats2half2_rn(v2, v3);
        }
    }
}

__global__ void __launch_bounds__(512, 2)
k_gemm(const __half* __restrict__ Wh, const float* __restrict__ blv,
       const float* __restrict__ brv, int n) {
    extern __shared__ __half smh[];
    int which = blockIdx.x & 1;
    gemm_body(Wh, which ? brv : blv, n, (blockIdx.x >> 1) * 128, which,
              smh, threadIdx.x);
}

// merged: gemm blocks [0, gB) + scatter blocks [gB, ...)
__global__ void __launch_bounds__(512, 2)
k_scatter_gemm(const __half* __restrict__ Wh, const float* __restrict__ blv,
               const float* __restrict__ brv,
               const int* ei, const float4* __restrict__ ea, int e, int n, int gB) {
    extern __shared__ __half smh[];
    if ((int)blockIdx.x < gB) {
        int which = blockIdx.x & 1;
        gemm_body(Wh, which ? brv : blv, n, (blockIdx.x >> 1) * 128, which,
                  smh, threadIdx.x);
        return;
    }
    int base = (blockIdx.x - gB) * 1024 + threadIdx.x;
    #pragma unroll
    for (int k = 0; k < 2; k++) {
        int idx = base + k * 512;
        if (idx < e) {
            int s = ei[idx], d = ei[e + idx];
            int pos = atomicAdd(&g_cnt[d], 1);
            g_csrc[pos] = s;
            float4 a = ea[idx];
            __half2 h0 = __floats2half2_rn(a.x, a.y);
            __half2 h1 = __floats2half2_rn(a.z, a.w);
            g_eah[pos] = make_uint2(*(unsigned*)&h0, *(unsigned*)&h1);
        }
    }
}

// ---- fused edge+softmax+aggregate+FiLM+LN+GELU+residual ----
// R11 structure (48-reg optimum); unconditional tail loads via +4 array padding
__global__ void k_node(const float* __restrict__ We, const float* __restrict__ att,
                       const float* __restrict__ cb, const float* __restrict__ lng,
                       const float* __restrict__ lnb, int n) {
    int tid = threadIdx.x;
    int warp = tid >> 5, lane = tid & 31;
    int i = blockIdx.x * 8 + warp;
    if (i >= n) return;

    float4 wf0 = ((const float4*)We)[lane];
    float4 wf1 = ((const float4*)We)[32 + lane];
    float4 wf2 = ((const float4*)We)[64 + lane];
    float4 wf3 = ((const float4*)We)[96 + lane];
    __half2 w0a = __floats2half2_rn(wf0.x, wf0.y), w0b = __floats2half2_rn(wf0.z, wf0.w);
    __half2 w1a = __floats2half2_rn(wf1.x, wf1.y), w1b = __floats2half2_rn(wf1.z, wf1.w);
    __half2 w2a = __floats2half2_rn(wf2.x, wf2.y), w2b = __floats2half2_rn(wf2.z, wf2.w);
    __half2 w3a = __floats2half2_rn(wf3.x, wf3.y), w3b = __floats2half2_rn(wf3.z, wf3.w);
    float4 atf = ((const float4*)att)[lane];
    __half2 at01 = __floats2half2_rn(atf.x, atf.y), at23 = __floats2half2_rn(atf.z, atf.w);
    uint2 xrr = ((const uint2*)g_xrh)[i * 32 + lane];
    __half2 xr01 = h2bits(xrr.x), xr23 = h2bits(xrr.y);
    const __half2 c02 = __float2half2_rn(0.2f);

    int beg = g_off[i], end = g_off[i + 1];
    float sme = 0.f;
    float4 acc = make_float4(0.f, 0.f, 0.f, 0.f);
    const uint2* xlh = (const uint2*)g_xlh;

    for (int j = beg; j < end; j += 4) {
        int c = end - j;
        // unconditional loads: slots [e, e+4) are zero-filled pad, contributions masked below
        int s0 = g_csrc[j];
        int s1 = g_csrc[j + 1];
        int s2 = g_csrc[j + 2];
        int s3 = g_csrc[j + 3];
        uint2 e0 = g_eah[j];
        uint2 e1 = g_eah[j + 1];
        uint2 e2 = g_eah[j + 2];
        uint2 e3 = g_eah[j + 3];
        uint2 r0 = xlh[s0 * 32 + lane];
        uint2 r1 = xlh[s1 * 32 + lane];
        uint2 r2 = xlh[s2 * 32 + lane];
        uint2 r3 = xlh[s3 * 32 + lane];

        float2 xa0, xb0, xa1, xb1, xa2, xb2, xa3, xb3;
        float p0, p1, p2, p3;
        #define EDGE_H2(rr, ed, xa, xb, pp)                                      \
        {                                                                        \
            __half2 xl01 = h2bits(rr.x), xl23 = h2bits(rr.y);                    \
            __half2 ex = h2bits(ed.x), ey = h2bits(ed.y);                        \
            __half2 b0 = __low2half2(ex), b1 = __high2half2(ex);                 \
            __half2 b2 = __low2half2(ey), b3 = __high2half2(ey);                 \
            __half2 m01 = __hadd2(xl01, xr01);                                   \
            m01 = __hfma2(b0, w0a, m01); m01 = __hfma2(b1, w1a, m01);            \
            m01 = __hfma2(b2, w2a, m01); m01 = __hfma2(b3, w3a, m01);            \
            __half2 m23 = __hadd2(xl23, xr23);                                   \
            m23 = __hfma2(b0, w0b, m23); m23 = __hfma2(b1, w1b, m23);            \
            m23 = __hfma2(b2, w2b, m23); m23 = __hfma2(b3, w3b, m23);            \
            m01 = __hmax2(m01, __hmul2(m01, c02));                               \
            m23 = __hmax2(m23, __hmul2(m23, c02));                               \
            __half2 pr = __hmul2(m01, at01);                                     \
            pr = __hfma2(m23, at23, pr);                                         \
            float2 pf = __half22float2(pr);                                      \
            pp = pf.x + pf.y;                                                    \
            xa = __half22float2(xl01);                                           \
            xb = __half22float2(xl23);                                           \
        }
        EDGE_H2(r0, e0, xa0, xb0, p0)
        EDGE_H2(r1, e1, xa1, xb1, p1)
        EDGE_H2(r2, e2, xa2, xb2, p2)
        EDGE_H2(r3, e3, xa3, xb3, p3)
        #undef EDGE_H2

        #pragma unroll
        for (int o = 1; o < 8; o <<= 1) {
            p0 += __shfl_xor_sync(0xFFFFFFFFu, p0, o);
            p1 += __shfl_xor_sync(0xFFFFFFFFu, p1, o);
            p2 += __shfl_xor_sync(0xFFFFFFFFu, p2, o);
            p3 += __shfl_xor_sync(0xFFFFFFFFu, p3, o);
        }
        float w0 = __expf(p0);
        float w1 = (c > 1) ? __expf(p1) : 0.f;
        float w2 = (c > 2) ? __expf(p2) : 0.f;
        float w3 = (c > 3) ? __expf(p3) : 0.f;
        sme += (w0 + w1) + (w2 + w3);
        acc.x += w0*xa0.x + w1*xa1.x + w2*xa2.x + w3*xa3.x;
        acc.y += w0*xa0.y + w1*xa1.y + w2*xa2.y + w3*xa3.y;
        acc.z += w0*xb0.x + w1*xb1.x + w2*xb2.x + w3*xb3.x;
        acc.w += w0*xb0.y + w1*xb1.y + w2*xb2.y + w3*xb3.y;
    }

    float inv = 1.0f / (sme + 1e-16f);
    float4 cb4 = ((const float4*)cb)[lane];
    float4 ga  = ((const float4*)g_gamma)[i * 32 + lane];
    float4 be  = ((const float4*)g_beta)[i * 32 + lane];
    float y0 = ga.x * (acc.x * inv + cb4.x) + be.x;
    float y1 = ga.y * (acc.y * inv + cb4.y) + be.y;
    float y2 = ga.z * (acc.z * inv + cb4.z) + be.z;
    float y3 = ga.w * (acc.w * inv + cb4.w) + be.w;
    float s1 = y0 + y1 + y2 + y3;
    float s2 = y0*y0 + y1*y1 + y2*y2 + y3*y3;
    #pragma unroll
    for (int o = 16; o > 0; o >>= 1) {
        s1 += __shfl_xor_sync(0xFFFFFFFFu, s1, o);
        s2 += __shfl_xor_sync(0xFFFFFFFFu, s2, o);
    }
    float mean = s1 * (1.0f / 128.0f);
    float var  = s2 * (1.0f / 128.0f) - mean * mean;
    float ivs  = rsqrtf(var + 1e-5f);
    float4 g4 = ((const float4*)lng)[lane];
    float4 b4 = ((const float4*)lnb)[lane];
    float4 ho = ((const float4*)g_h)[i * 32 + lane];
    float4 out;
    out.x = gelu_f((y0 - mean) * ivs * g4.x + b4.x) + ho.x;
    out.y = gelu_f((y1 - mean) * ivs * g4.y + b4.y) + ho.y;
    out.z = gelu_f((y2 - mean) * ivs * g4.z + b4.z) + ho.z;
    out.w = gelu_f((y3 - mean) * ivs * g4.w + b4.w) + ho.w;
    ((float4*)g_h)[i * 32 + lane] = out;
    __half2 o0 = __floats2half2_rn(out.x, out.y);
    __half2 o1 = __floats2half2_rn(out.z, out.w);
    uint2 pk;
    pk.x = *(unsigned*)&o0;
    pk.y = *(unsigned*)&o1;
    ((uint2*)g_hh)[i * 32 + lane] = pk;
}

// ---------------- decoder + mask + output (+ reset counters) ----------------
__global__ void k_dec(const float* __restrict__ W1, const float* __restrict__ b1,
                      const float* __restrict__ W2, const float* __restrict__ b2,
                      const float* __restrict__ x, const void* __restrict__ mask,
                      float* __restrict__ out, int n, int out_size) {
    __shared__ float sW1[8192];
    __shared__ float sW2[128];
    __shared__ float sb1v[64];
    __shared__ float sb2v[2];
    __shared__ float sH[8][128];
    int tid = threadIdx.x;
    int gid = blockIdx.x * blockDim.x + tid;
    if (gid < n) g_cnt[gid] = 0;
    if (gid < 2) g_viol[gid] = 0;
    for (int i = tid; i < 8192; i += 256) sW1[i] = W1[i];
    if (tid < 128) sW2[tid] = W2[tid];
    if (tid < 64) sb1v[tid] = b1[tid];
    if (tid < 2) sb2v[tid] = b2[tid];
    __syncthreads();
    int warp = tid >> 5, lane = tid & 31;
    int mode = g_maskmode;
    for (int i = blockIdx.x * 8 + warp; i < n; i += gridDim.x * 8) {
        #pragma unroll
        for (int h = 0; h < 4; h++) sH[warp][h * 32 + lane] = g_h[i * 128 + h * 32 + lane];
        __syncwarp();
        float a0 = sb1v[lane], a1 = sb1v[lane + 32];
        for (int k = 0; k < 128; k++) {
            float hv = sH[warp][k];
            a0 += hv * sW1[k * 64 + lane];
            a1 += hv * sW1[k * 64 + lane + 32];
        }
        float t0 = gelu_f(a0), t1 = gelu_f(a1);
        float d0 = t0 * sW2[lane * 2]     + t1 * sW2[(lane + 32) * 2];
        float d1 = t0 * sW2[lane * 2 + 1] + t1 * sW2[(lane + 32) * 2 + 1];
        #pragma unroll
        for (int o = 16; o > 0; o >>= 1) {
            d0 += __shfl_xor_sync(0xFFFFFFFFu, d0, o);
            d1 += __shfl_xor_sync(0xFFFFFFFFu, d1, o);
        }
        if (lane == 0) {
            d0 += sb2v[0]; d1 += sb2v[1];
            int fixed;
            if (mode == 0)      fixed = ((const int*)mask)[i] != 0;
            else if (mode == 1) fixed = ((const float*)mask)[i] != 0.f;
            else                fixed = ((const unsigned char*)mask)[i] != 0;
            if (fixed) { d0 = 0.f; d1 = 0.f; }
            out[i * 2]     = x[i * 6]     + d0;
            out[i * 2 + 1] = x[i * 6 + 1] + d1;
            if (out_size >= 4 * n) {
                out[2 * n + i * 2]     = d0;
                out[2 * n + i * 2 + 1] = d1;
            }
        }
        __syncwarp();
    }
}

// ---------------- launch ----------------
extern "C" void kernel_launch(void* const* d_in, const int* in_sizes, int n_in,
                              void* d_out, int out_size) {
    const float* x    = (const float*)d_in[0];
    const int*   ei   = (const int*)d_in[1];
    const float* ea   = (const float*)d_in[2];
    const float* tmp  = (const float*)d_in[3];
    const void*  mask = d_in[4];
    const float* encW = (const float*)d_in[5];
    const float* encB = (const float*)d_in[6];
    const float* encG = (const float*)d_in[7];
    const float* encBe= (const float*)d_in[8];
    const float* fW1  = (const float*)d_in[9];
    const float* fb1  = (const float*)d_in[10];
    const float* fW2  = (const float*)d_in[11];
    const float* fb2  = (const float*)d_in[12];
    const float* Wl   = (const float*)d_in[13];
    const float* bl   = (const float*)d_in[14];
    const float* Wr   = (const float*)d_in[15];
    const float* br   = (const float*)d_in[16];
    const float* We   = (const float*)d_in[17];
    const float* att  = (const float*)d_in[18];
    const float* cb   = (const float*)d_in[19];
    const float* lng  = (const float*)d_in[20];
    const float* lnb  = (const float*)d_in[21];
    const float* dW1  = (const float*)d_in[22];
    const float* db1  = (const float*)d_in[23];
    const float* dW2  = (const float*)d_in[24];
    const float* db2  = (const float*)d_in[25];
    float* out = (float*)d_out;

    int n = in_sizes[0] / 6;
    int e = in_sizes[2] / 4;

    const int gemm_smem = 256 * AST * 2;                // 69632
    const int prep_smem = (17536 + 2048) * 4;           // 78336
    cudaFuncSetAttribute(k_scan_prep, cudaFuncAttributeMaxDynamicSharedMemorySize, prep_smem);
    cudaFuncSetAttribute(k_gemm, cudaFuncAttributeMaxDynamicSharedMemorySize, gemm_smem);
    cudaFuncSetAttribute(k_scatter_gemm, cudaFuncAttributeMaxDynamicSharedMemorySize, gemm_smem);

    int gB = 2 * ((n + 127) / 128);     // 2 half-gemm blocks per 128-row tile
    int sB = (e + 1023) / 1024;

    __half* Wh = nullptr;
    cudaGetSymbolAddress((void**)&Wh, g_Wh);

    // launches: count(0), scan_prep(1), scatter_gemm0(2), node0(3) <- profiled
    k_count<<<(e + 255) / 256, 256>>>(ei, (const int*)mask, Wl, Wr, e, n);
    k_scan_prep<<<201, 1024, prep_smem>>>(x, tmp, encW, encB, encG, encBe,
                                          fW1, fb1, fW2, fb2, n);
    k_scatter_gemm<<<gB + sB, 512, gemm_smem>>>(Wh, bl, br,
                                                ei, (const float4*)ea, e, n, gB);
    k_node<<<(n + 7) / 8, 256>>>(We, att, cb, lng, lnb, n);

    for (int l = 1; l < 4; l++) {
        k_gemm<<<gB, 512, gemm_smem>>>(Wh + l * 32768, bl + l * 128,
                                       br + l * 128, n);
        k_node<<<(n + 7) / 8, 256>>>(We + l * 512, att + l * 128,
                                     cb + l * 128, lng + l * 128, lnb + l * 128, n);
    }

    k_dec<<<1536, 256>>>(dW1, db1, dW2, db2, x, mask, out, n, out_size);
}

// round 15
// speedup vs baseline: 1.0611x; 1.0226x over previous
#include <cuda_runtime.h>
#include <cuda_fp16.h>
#include <math.h>

#define HID 128
#define NMAX 50048
#define EMAX 1600000

// ---------------- device scratch ----------------
__device__ float   g_h[NMAX * HID];       // fp32 h (residual + decoder)
__device__ __half  g_hh[NMAX * HID];      // fp16 h (GEMM input)
__device__ __half2 g_xlh[NMAX * 64];      // xl fp16 (gather payload)
__device__ __half2 g_xrh[NMAX * 64];      // xr fp16
__device__ float   g_gamma[NMAX * HID];
__device__ float   g_beta[NMAX * HID];
__device__ uint2   g_eah[EMAX];           // edge_attr fp16 x4, CSR-permuted
__device__ __half  g_Wh[4 * 256 * 128];   // [layer][n:256][k:128] fp16 weights
__device__ int     g_off[NMAX + 1];
__device__ int     g_cnt[NMAX];           // zero-init at load; re-zeroed by k_dec
__device__ int     g_csrc[EMAX];
__device__ int     g_perm[NMAX];          // nodes sorted by degree
__device__ int     g_viol[2];
__device__ int     g_maskmode;

__device__ __forceinline__ float gelu_f(float x) {
    return 0.5f * x * (1.0f + erff(x * 0.7071067811865476f));
}
__device__ __forceinline__ __half2 h2bits(unsigned u) { return *(__half2*)&u; }

// ---------------- CSR count + mask detect + weight fp16 conversion ----------------
__global__ void k_count(const int* ei, const int* m,
                        const float* __restrict__ Wl, const float* __restrict__ Wr,
                        int e, int n) {
    int i = blockIdx.x * blockDim.x + threadIdx.x;
    if (i < e) atomicAdd(&g_cnt[ei[e + i]], 1);
    int words = n >> 2;
    int lim = words < 8192 ? words : 8192;
    if (i < lim) {
        int v = m[i];
        if (v != 0 && v != 1) atomicOr(&g_viol[0], 1);
        if (v != 0 && v != 0x3F800000) atomicOr(&g_viol[1], 1);
    }
    if (i < 4 * 32768) {
        int l = i >> 15, rem = i & 32767;
        int nn = rem & 255, kk = rem >> 8;
        float v = (nn < 128) ? Wl[l * 16384 + kk * 128 + nn]
                             : Wr[l * 16384 + kk * 128 + nn - 128];
        g_Wh[(l << 15) + nn * 128 + kk] = __float2half_rn(v);
    }
}

// ---------------- merged: block 0 = scan + degree sort, blocks 1.. = prep ----------------
__global__ void k_scan_prep(const float* __restrict__ x, const float* __restrict__ tmp,
                            const float* __restrict__ encW, const float* __restrict__ encB,
                            const float* __restrict__ encG, const float* __restrict__ encBe,
                            const float* __restrict__ fW1, const float* __restrict__ fb1,
                            const float* __restrict__ fW2, const float* __restrict__ fb2,
                            int n) {
    int tid = threadIdx.x;
    if (blockIdx.x == 0) {
        __shared__ int warpsum[32];
        __shared__ int hist[512];
        __shared__ int basebin[512];
        int t = tid;
        int per = (n + 1023) >> 10;
        int i0 = t * per;
        int i1 = i0 + per; if (i1 > n) i1 = n; if (i0 > n) i0 = n;
        int local = 0;
        for (int i = i0; i < i1; i++) local += g_cnt[i];
        int lane = t & 31, warp = t >> 5;
        int v = local;
        #pragma unroll
        for (int o = 1; o < 32; o <<= 1) {
            int u = __shfl_up_sync(0xFFFFFFFFu, v, o);
            if (lane >= o) v += u;
        }
        if (lane == 31) warpsum[warp] = v;
        __syncthreads();
        if (warp == 0) {
            int w = warpsum[lane];
            #pragma unroll
            for (int o = 1; o < 32; o <<= 1) {
                int u = __shfl_up_sync(0xFFFFFFFFu, w, o);
                if (lane >= o) w += u;
            }
            warpsum[lane] = w;
        }
        __syncthreads();
        int excl = v - local + (warp ? warpsum[warp - 1] : 0);
        int run = excl;
        for (int i = i0; i < i1; i++) {
            int c = g_cnt[i];
            g_off[i] = run;
            g_cnt[i] = run;
            run += c;
        }
        if (t == 1023) g_off[n] = run;
        if (t == 0) g_maskmode = (g_viol[0] == 0) ? 0 : ((g_viol[1] == 0) ? 1 : 2);

        // ---- degree-sort permutation (counting sort, 512 bins) ----
        for (int k = tid; k < 512; k += 1024) hist[k] = 0;
        __syncthreads();          // also ensures all g_off written
        for (int i = i0; i < i1; i++) {
            int d = g_off[i + 1] - g_off[i];
            if (d > 511) d = 511;
            atomicAdd(&hist[d], 1);
        }
        __syncthreads();
        int hv = 0, hincl = 0;
        if (tid < 512) {
            hv = hist[tid];
            hincl = hv;
            #pragma unroll
            for (int o = 1; o < 32; o <<= 1) {
                int u = __shfl_up_sync(0xFFFFFFFFu, hincl, o);
                if (lane >= o) hincl += u;
            }
            if (lane == 31) warpsum[warp] = hincl;   // warps 0..15
        }
        __syncthreads();
        if (warp == 0 && lane < 16) {
            int w = warpsum[lane];
            #pragma unroll
            for (int o = 1; o < 16; o <<= 1) {
                int u = __shfl_up_sync(0x0000FFFFu, w, o);
                if (lane >= o) w += u;
            }
            warpsum[lane] = w;
        }
        __syncthreads();
        if (tid < 512) {
            basebin[tid] = hincl - hv + (warp ? warpsum[warp - 1] : 0);
            hist[tid] = 0;       // reuse as cursor
        }
        __syncthreads();
        for (int i = i0; i < i1; i++) {
            int d = g_off[i + 1] - g_off[i];
            if (d > 511) d = 511;
            int pos = basebin[d] + atomicAdd(&hist[d], 1);
            g_perm[pos] = i;
        }
        return;
    }
    extern __shared__ float sm[];
    float* sEncW = sm;            // 768
    float* sW1   = sm + 768;      // 64
    float* sB1   = sm + 832;      // 64
    float* sB2   = sm + 896;      // 256
    float* sW2   = sm + 1152;     // 16384
    float* sT1   = sm + 17536;    // 2048 (32 warps x 64)
    for (int i = tid; i < 768; i += blockDim.x) sEncW[i] = encW[i];
    for (int i = tid; i < 64; i += blockDim.x) { sW1[i] = fW1[i]; sB1[i] = fb1[i]; }
    for (int i = tid; i < 256; i += blockDim.x) sB2[i] = fb2[i];
    for (int i = tid; i < 4096; i += blockDim.x)
        ((float4*)sW2)[i] = ((const float4*)fW2)[i];
    __syncthreads();
    int warp = tid >> 5, lane = tid & 31;
    int nb = gridDim.x - 1, pb = blockIdx.x - 1;
    for (int i = pb * 32 + warp; i < n; i += nb * 32) {
        float xv[6];
        #pragma unroll
        for (int j = 0; j < 6; j++) xv[j] = x[i * 6 + j];
        float y[4];
        #pragma unroll
        for (int h = 0; h < 4; h++) {
            int k = h * 32 + lane;
            float a = encB[k];
            #pragma unroll
            for (int j = 0; j < 6; j++) a += xv[j] * sEncW[j * 128 + k];
            y[h] = a;
        }
        float s1 = y[0] + y[1] + y[2] + y[3];
        float s2 = y[0]*y[0] + y[1]*y[1] + y[2]*y[2] + y[3]*y[3];
        #pragma unroll
        for (int o = 16; o > 0; o >>= 1) {
            s1 += __shfl_xor_sync(0xFFFFFFFFu, s1, o);
            s2 += __shfl_xor_sync(0xFFFFFFFFu, s2, o);
        }
        float mean = s1 * (1.0f / 128.0f);
        float var  = s2 * (1.0f / 128.0f) - mean * mean;
        float inv  = rsqrtf(var + 1e-5f);
        #pragma unroll
        for (int h = 0; h < 4; h++) {
            int k = h * 32 + lane;
            float v = (y[h] - mean) * inv * encG[k] + encBe[k];
            float g = gelu_f(v);
            g_h[i * 128 + k]  = g;
            g_hh[i * 128 + k] = __float2half_rn(g);
        }
        float tm = tmp[i];
        #pragma unroll
        for (int c = 0; c < 2; c++) {
            int j = lane + 32 * c;
            sT1[warp * 64 + j] = gelu_f(tm * sW1[j] + sB1[j]);
        }
        __syncwarp();
        float f[8];
        #pragma unroll
        for (int c = 0; c < 8; c++) f[c] = sB2[lane + 32 * c];
        for (int j = 0; j < 64; j++) {
            float t = sT1[warp * 64 + j];
            #pragma unroll
            for (int c = 0; c < 8; c++) f[c] += t * sW2[j * 256 + lane + 32 * c];
        }
        #pragma unroll
        for (int c = 0; c < 4; c++) {
            g_gamma[i * 128 + lane + 32 * c] = f[c];
            g_beta[i * 128 + lane + 32 * c]  = f[c + 4];
        }
        __syncwarp();
    }
}

// ---------------- tensor-core half-GEMM body ----------------
#define AST 136   // padded k-stride (halfs)
__device__ __forceinline__ void gemm_body(
    const __half* __restrict__ Wh, const float* __restrict__ bias,
    int n, int row0, int which, __half* smh, int tid) {
    __half* As = smh;               // 128 x 136
    __half* Bs = smh + 128 * AST;   // 128 x 136

    for (int idx = tid; idx < 2048; idx += 512) {
        int row = idx >> 4, c8 = idx & 15;
        int gr = row0 + row;
        uint4 v = make_uint4(0, 0, 0, 0);
        if (gr < n) v = ((const uint4*)g_hh)[gr * 16 + c8];
        *(uint4*)&As[row * AST + c8 * 8] = v;
    }
    const __half* Wsel = Wh + which * 16384;
    for (int idx = tid; idx < 2048; idx += 512) {
        int nn = idx >> 4, c8 = idx & 15;
        uint4 v = ((const uint4*)(Wsel + nn * 128))[c8];
        *(uint4*)&Bs[nn * AST + c8 * 8] = v;
    }
    __syncthreads();

    int warp = tid >> 5, lane = tid & 31;
    int mi = warp & 3, ni = warp >> 2;
    int gid = lane >> 2, tig = lane & 3;

    float d[2][4][4];
    #pragma unroll
    for (int tm = 0; tm < 2; tm++)
        #pragma unroll
        for (int tn = 0; tn < 4; tn++)
            #pragma unroll
            for (int q = 0; q < 4; q++) d[tm][tn][q] = 0.f;

    #pragma unroll
    for (int ks = 0; ks < 8; ks++) {
        int k0 = ks * 16;
        unsigned a[2][4];
        #pragma unroll
        for (int tm = 0; tm < 2; tm++) {
            int r = mi * 32 + tm * 16 + gid;
            a[tm][0] = *(const unsigned*)&As[r * AST + k0 + tig * 2];
            a[tm][1] = *(const unsigned*)&As[(r + 8) * AST + k0 + tig * 2];
            a[tm][2] = *(const unsigned*)&As[r * AST + k0 + tig * 2 + 8];
            a[tm][3] = *(const unsigned*)&As[(r + 8) * AST + k0 + tig * 2 + 8];
        }
        unsigned b[4][2];
        #pragma unroll
        for (int tn = 0; tn < 4; tn++) {
            int nn = ni * 32 + tn * 8 + gid;
            b[tn][0] = *(const unsigned*)&Bs[nn * AST + k0 + tig * 2];
            b[tn][1] = *(const unsigned*)&Bs[nn * AST + k0 + tig * 2 + 8];
        }
        #pragma unroll
        for (int tm = 0; tm < 2; tm++)
            #pragma unroll
            for (int tn = 0; tn < 4; tn++) {
                asm volatile(
                    "mma.sync.aligned.m16n8k16.row.col.f32.f16.f16.f32 "
                    "{%0,%1,%2,%3}, {%4,%5,%6,%7}, {%8,%9}, {%0,%1,%2,%3};\n"
                    : "+f"(d[tm][tn][0]), "+f"(d[tm][tn][1]),
                      "+f"(d[tm][tn][2]), "+f"(d[tm][tn][3])
                    : "r"(a[tm][0]), "r"(a[tm][1]), "r"(a[tm][2]), "r"(a[tm][3]),
                      "r"(b[tn][0]), "r"(b[tn][1]));
            }
    }

    __half2* dst = which ? g_xrh : g_xlh;
    #pragma unroll
    for (int tn = 0; tn < 4; tn++) {
        int nglob = ni * 32 + tn * 8 + tig * 2;   // 0..127
        float b0 = bias[nglob], b1 = bias[nglob + 1];
        #pragma unroll
        for (int tm = 0; tm < 2; tm++) {
            int r0 = row0 + mi * 32 + tm * 16 + gid;
            int r1 = r0 + 8;
            float v0 = d[tm][tn][0] + b0, v1 = d[tm][tn][1] + b1;
            float v2 = d[tm][tn][2] + b0, v3 = d[tm][tn][3] + b1;
            int c = nglob >> 1;
            if (r0 < n) dst[r0 * 64 + c] = __floats2half2_rn(v0, v1);
            if (r1 < n) dst[r1 * 64 + c] = __floats2half2_rn(v2, v3);
        }
    }
}

__global__ void __launch_bounds__(512, 2)
k_gemm(const __half* __restrict__ Wh, const float* __restrict__ blv,
       const float* __restrict__ brv, int n) {
    extern __shared__ __half smh[];
    int which = blockIdx.x & 1;
    gemm_body(Wh, which ? brv : blv, n, (blockIdx.x >> 1) * 128, which,
              smh, threadIdx.x);
}

// merged: gemm blocks [0, gB) + scatter blocks [gB, ...)
__global__ void __launch_bounds__(512, 2)
k_scatter_gemm(const __half* __restrict__ Wh, const float* __restrict__ blv,
               const float* __restrict__ brv,
               const int* ei, const float4* __restrict__ ea, int e, int n, int gB) {
    extern __shared__ __half smh[];
    if ((int)blockIdx.x < gB) {
        int which = blockIdx.x & 1;
        gemm_body(Wh, which ? brv : blv, n, (blockIdx.x >> 1) * 128, which,
                  smh, threadIdx.x);
        return;
    }
    int base = (blockIdx.x - gB) * 1024 + threadIdx.x;
    #pragma unroll
    for (int k = 0; k < 2; k++) {
        int idx = base + k * 512;
        if (idx < e) {
            int s = ei[idx], d = ei[e + idx];
            int pos = atomicAdd(&g_cnt[d], 1);
            g_csrc[pos] = s;
            float4 a = ea[idx];
            __half2 h0 = __floats2half2_rn(a.x, a.y);
            __half2 h1 = __floats2half2_rn(a.z, a.w);
            g_eah[pos] = make_uint2(*(unsigned*)&h0, *(unsigned*)&h1);
        }
    }
}

// ---- fused edge+softmax+aggregate+FiLM+LN+GELU+residual ----
// R11 inner loop (frozen, 48-reg optimum); degree-sorted node scheduling via g_perm
__global__ void k_node(const float* __restrict__ We, const float* __restrict__ att,
                       const float* __restrict__ cb, const float* __restrict__ lng,
                       const float* __restrict__ lnb, int n) {
    int tid = threadIdx.x;
    int warp = tid >> 5, lane = tid & 31;
    int idx = blockIdx.x * 8 + warp;
    if (idx >= n) return;
    int i = g_perm[idx];

    float4 wf0 = ((const float4*)We)[lane];
    float4 wf1 = ((const float4*)We)[32 + lane];
    float4 wf2 = ((const float4*)We)[64 + lane];
    float4 wf3 = ((const float4*)We)[96 + lane];
    __half2 w0a = __floats2half2_rn(wf0.x, wf0.y), w0b = __floats2half2_rn(wf0.z, wf0.w);
    __half2 w1a = __floats2half2_rn(wf1.x, wf1.y), w1b = __floats2half2_rn(wf1.z, wf1.w);
    __half2 w2a = __floats2half2_rn(wf2.x, wf2.y), w2b = __floats2half2_rn(wf2.z, wf2.w);
    __half2 w3a = __floats2half2_rn(wf3.x, wf3.y), w3b = __floats2half2_rn(wf3.z, wf3.w);
    float4 atf = ((const float4*)att)[lane];
    __half2 at01 = __floats2half2_rn(atf.x, atf.y), at23 = __floats2half2_rn(atf.z, atf.w);
    uint2 xrr = ((const uint2*)g_xrh)[i * 32 + lane];
    __half2 xr01 = h2bits(xrr.x), xr23 = h2bits(xrr.y);
    const __half2 c02 = __float2half2_rn(0.2f);

    int beg = g_off[i], end = g_off[i + 1];
    float sme = 0.f;
    float4 acc = make_float4(0.f, 0.f, 0.f, 0.f);
    const uint2* xlh = (const uint2*)g_xlh;

    for (int j = beg; j < end; j += 4) {
        int c = end - j;
        int s0 = g_csrc[j];
        int s1 = (c > 1) ? g_csrc[j + 1] : s0;
        int s2 = (c > 2) ? g_csrc[j + 2] : s0;
        int s3 = (c > 3) ? g_csrc[j + 3] : s0;
        uint2 e0 = g_eah[j];
        uint2 e1 = (c > 1) ? g_eah[j + 1] : e0;
        uint2 e2 = (c > 2) ? g_eah[j + 2] : e0;
        uint2 e3 = (c > 3) ? g_eah[j + 3] : e0;
        uint2 r0 = xlh[s0 * 32 + lane];
        uint2 r1 = xlh[s1 * 32 + lane];
        uint2 r2 = xlh[s2 * 32 + lane];
        uint2 r3 = xlh[s3 * 32 + lane];

        float2 xa0, xb0, xa1, xb1, xa2, xb2, xa3, xb3;
        float p0, p1, p2, p3;
        #define EDGE_H2(rr, ed, xa, xb, pp)                                      \
        {                                                                        \
            __half2 xl01 = h2bits(rr.x), xl23 = h2bits(rr.y);                    \
            __half2 ex = h2bits(ed.x), ey = h2bits(ed.y);                        \
            __half2 b0 = __low2half2(ex), b1 = __high2half2(ex);                 \
            __half2 b2 = __low2half2(ey), b3 = __high2half2(ey);                 \
            __half2 m01 = __hadd2(xl01, xr01);                                   \
            m01 = __hfma2(b0, w0a, m01); m01 = __hfma2(b1, w1a, m01);            \
            m01 = __hfma2(b2, w2a, m01); m01 = __hfma2(b3, w3a, m01);            \
            __half2 m23 = __hadd2(xl23, xr23);                                   \
            m23 = __hfma2(b0, w0b, m23); m23 = __hfma2(b1, w1b, m23);            \
            m23 = __hfma2(b2, w2b, m23); m23 = __hfma2(b3, w3b, m23);            \
            m01 = __hmax2(m01, __hmul2(m01, c02));                               \
            m23 = __hmax2(m23, __hmul2(m23, c02));                               \
            __half2 pr = __hmul2(m01, at01);                                     \
            pr = __hfma2(m23, at23, pr);                                         \
            float2 pf = __half22float2(pr);                                      \
            pp = pf.x + pf.y;                                                    \
            xa = __half22float2(xl01);                                           \
            xb = __half22float2(xl23);                                           \
        }
        EDGE_H2(r0, e0, xa0, xb0, p0)
        EDGE_H2(r1, e1, xa1, xb1, p1)
        EDGE_H2(r2, e2, xa2, xb2, p2)
        EDGE_H2(r3, e3, xa3, xb3, p3)
        #undef EDGE_H2

        #pragma unroll
        for (int o = 1; o < 8; o <<= 1) {
            p0 += __shfl_xor_sync(0xFFFFFFFFu, p0, o);
            p1 += __shfl_xor_sync(0xFFFFFFFFu, p1, o);
            p2 += __shfl_xor_sync(0xFFFFFFFFu, p2, o);
            p3 += __shfl_xor_sync(0xFFFFFFFFu, p3, o);
        }
        float w0 = __expf(p0);
        float w1 = (c > 1) ? __expf(p1) : 0.f;
        float w2 = (c > 2) ? __expf(p2) : 0.f;
        float w3 = (c > 3) ? __expf(p3) : 0.f;
        sme += (w0 + w1) + (w2 + w3);
        acc.x += w0*xa0.x + w1*xa1.x + w2*xa2.x + w3*xa3.x;
        acc.y += w0*xa0.y + w1*xa1.y + w2*xa2.y + w3*xa3.y;
        acc.z += w0*xb0.x + w1*xb1.x + w2*xb2.x + w3*xb3.x;
        acc.w += w0*xb0.y + w1*xb1.y + w2*xb2.y + w3*xb3.y;
    }

    float inv = 1.0f / (sme + 1e-16f);
    float4 cb4 = ((const float4*)cb)[lane];
    float4 ga  = ((const float4*)g_gamma)[i * 32 + lane];
    float4 be  = ((const float4*)g_beta)[i * 32 + lane];
    float y0 = ga.x * (acc.x * inv + cb4.x) + be.x;
    float y1 = ga.y * (acc.y * inv + cb4.y) + be.y;
    float y2 = ga.z * (acc.z * inv + cb4.z) + be.z;
    float y3 = ga.w * (acc.w * inv + cb4.w) + be.w;
    float s1 = y0 + y1 + y2 + y3;
    float s2 = y0*y0 + y1*y1 + y2*y2 + y3*y3;
    #pragma unroll
    for (int o = 16; o > 0; o >>= 1) {
        s1 += __shfl_xor_sync(0xFFFFFFFFu, s1, o);
        s2 += __shfl_xor_sync(0xFFFFFFFFu, s2, o);
    }
    float mean = s1 * (1.0f / 128.0f);
    float var  = s2 * (1.0f / 128.0f) - mean * mean;
    float ivs  = rsqrtf(var + 1e-5f);
    float4 g4 = ((const float4*)lng)[lane];
    float4 b4 = ((const float4*)lnb)[lane];
    float4 ho = ((const float4*)g_h)[i * 32 + lane];
    float4 out;
    out.x = gelu_f((y0 - mean) * ivs * g4.x + b4.x) + ho.x;
    out.y = gelu_f((y1 - mean) * ivs * g4.y + b4.y) + ho.y;
    out.z = gelu_f((y2 - mean) * ivs * g4.z + b4.z) + ho.z;
    out.w = gelu_f((y3 - mean) * ivs * g4.w + b4.w) + ho.w;
    ((float4*)g_h)[i * 32 + lane] = out;
    __half2 o0 = __floats2half2_rn(out.x, out.y);
    __half2 o1 = __floats2half2_rn(out.z, out.w);
    uint2 pk;
    pk.x = *(unsigned*)&o0;
    pk.y = *(unsigned*)&o1;
    ((uint2*)g_hh)[i * 32 + lane] = pk;
}

// ---------------- decoder + mask + output (+ reset counters) ----------------
__global__ void k_dec(const float* __restrict__ W1, const float* __restrict__ b1,
                      const float* __restrict__ W2, const float* __restrict__ b2,
                      const float* __restrict__ x, const void* __restrict__ mask,
                      float* __restrict__ out, int n, int out_size) {
    __shared__ float sW1[8192];
    __shared__ float sW2[128];
    __shared__ float sb1v[64];
    __shared__ float sb2v[2];
    __shared__ float sH[8][128];
    int tid = threadIdx.x;
    int gid = blockIdx.x * blockDim.x + tid;
    if (gid < n) g_cnt[gid] = 0;
    if (gid < 2) g_viol[gid] = 0;
    for (int i = tid; i < 8192; i += 256) sW1[i] = W1[i];
    if (tid < 128) sW2[tid] = W2[tid];
    if (tid < 64) sb1v[tid] = b1[tid];
    if (tid < 2) sb2v[tid] = b2[tid];
    __syncthreads();
    int warp = tid >> 5, lane = tid & 31;
    int mode = g_maskmode;
    for (int i = blockIdx.x * 8 + warp; i < n; i += gridDim.x * 8) {
        #pragma unroll
        for (int h = 0; h < 4; h++) sH[warp][h * 32 + lane] = g_h[i * 128 + h * 32 + lane];
        __syncwarp();
        float a0 = sb1v[lane], a1 = sb1v[lane + 32];
        for (int k = 0; k < 128; k++) {
            float hv = sH[warp][k];
            a0 += hv * sW1[k * 64 + lane];
            a1 += hv * sW1[k * 64 + lane + 32];
        }
        float t0 = gelu_f(a0), t1 = gelu_f(a1);
        float d0 = t0 * sW2[lane * 2]     + t1 * sW2[(lane + 32) * 2];
        float d1 = t0 * sW2[lane * 2 + 1] + t1 * sW2[(lane + 32) * 2 + 1];
        #pragma unroll
        for (int o = 16; o > 0; o >>= 1) {
            d0 += __shfl_xor_sync(0xFFFFFFFFu, d0, o);
            d1 += __shfl_xor_sync(0xFFFFFFFFu, d1, o);
        }
        if (lane == 0) {
            d0 += sb2v[0]; d1 += sb2v[1];
            int fixed;
            if (mode == 0)      fixed = ((const int*)mask)[i] != 0;
            else if (mode == 1) fixed = ((const float*)mask)[i] != 0.f;
            else                fixed = ((const unsigned char*)mask)[i] != 0;
            if (fixed) { d0 = 0.f; d1 = 0.f; }
            out[i * 2]     = x[i * 6]     + d0;
            out[i * 2 + 1] = x[i * 6 + 1] + d1;
            if (out_size >= 4 * n) {
                out[2 * n + i * 2]     = d0;
                out[2 * n + i * 2 + 1] = d1;
            }
        }
        __syncwarp();
    }
}

// ---------------- launch ----------------
extern "C" void kernel_launch(void* const* d_in, const int* in_sizes, int n_in,
                              void* d_out, int out_size) {
    const float* x    = (const float*)d_in[0];
    const int*   ei   = (const int*)d_in[1];
    const float* ea   = (const float*)d_in[2];
    const float* tmp  = (const float*)d_in[3];
    const void*  mask = d_in[4];
    const float* encW = (const float*)d_in[5];
    const float* encB = (const float*)d_in[6];
    const float* encG = (const float*)d_in[7];
    const float* encBe= (const float*)d_in[8];
    const float* fW1  = (const float*)d_in[9];
    const float* fb1  = (const float*)d_in[10];
    const float* fW2  = (const float*)d_in[11];
    const float* fb2  = (const float*)d_in[12];
    const float* Wl   = (const float*)d_in[13];
    const float* bl   = (const float*)d_in[14];
    const float* Wr   = (const float*)d_in[15];
    const float* br   = (const float*)d_in[16];
    const float* We   = (const float*)d_in[17];
    const float* att  = (const float*)d_in[18];
    const float* cb   = (const float*)d_in[19];
    const float* lng  = (const float*)d_in[20];
    const float* lnb  = (const float*)d_in[21];
    const float* dW1  = (const float*)d_in[22];
    const float* db1  = (const float*)d_in[23];
    const float* dW2  = (const float*)d_in[24];
    const float* db2  = (const float*)d_in[25];
    float* out = (float*)d_out;

    int n = in_sizes[0] / 6;
    int e = in_sizes[2] / 4;

    const int gemm_smem = 256 * AST * 2;                // 69632
    const int prep_smem = (17536 + 2048) * 4;           // 78336
    cudaFuncSetAttribute(k_scan_prep, cudaFuncAttributeMaxDynamicSharedMemorySize, prep_smem);
    cudaFuncSetAttribute(k_gemm, cudaFuncAttributeMaxDynamicSharedMemorySize, gemm_smem);
    cudaFuncSetAttribute(k_scatter_gemm, cudaFuncAttributeMaxDynamicSharedMemorySize, gemm_smem);

    int gB = 2 * ((n + 127) / 128);     // 2 half-gemm blocks per 128-row tile
    int sB = (e + 1023) / 1024;

    __half* Wh = nullptr;
    cudaGetSymbolAddress((void**)&Wh, g_Wh);

    // launches: count(0), scan_prep(1), scatter_gemm0(2), node0(3) <- profiled
    k_count<<<(e + 255) / 256, 256>>>(ei, (const int*)mask, Wl, Wr, e, n);
    k_scan_prep<<<201, 1024, prep_smem>>>(x, tmp, encW, encB, encG, encBe,
                                          fW1, fb1, fW2, fb2, n);
    k_scatter_gemm<<<gB + sB, 512, gemm_smem>>>(Wh, bl, br,
                                                ei, (const float4*)ea, e, n, gB);
    k_node<<<(n + 7) / 8, 256>>>(We, att, cb, lng, lnb, n);

    for (int l = 1; l < 4; l++) {
        k_gemm<<<gB, 512, gemm_smem>>>(Wh + l * 32768, bl + l * 128,
                                       br + l * 128, n);
        k_node<<<(n + 7) / 8, 256>>>(We + l * 512, att + l * 128,
                                     cb + l * 128, lng + l * 128, lnb + l * 128, n);
    }

    k_dec<<<1536, 256>>>(dW1, db1, dW2, db2, x, mask, out, n, out_size);
}

// round 16
// speedup vs baseline: 1.0752x; 1.0133x over previous
#include <cuda_runtime.h>
#include <cuda_fp16.h>
#include <math.h>

#define HID 128
#define NMAX 50048
#define EMAX 1600000

// ---------------- device scratch ----------------
__device__ __half  g_hh[NMAX * HID];      // h in fp16 (residual + GEMM input + decoder)
__device__ __half2 g_xlh[NMAX * 64];      // xl fp16 (gather payload)
__device__ __half2 g_xrh[NMAX * 64];      // xr fp16
__device__ float   g_gamma[NMAX * HID];
__device__ float   g_beta[NMAX * HID];
__device__ uint2   g_eah[EMAX];           // edge_attr fp16 x4, CSR-permuted
__device__ __half  g_Wh[4 * 256 * 128];   // [layer][n:256][k:128] fp16 weights
__device__ int     g_off[NMAX + 1];
__device__ int     g_cnt[NMAX];           // zero-init at load; re-zeroed by k_dec
__device__ int     g_csrc[EMAX];
__device__ int     g_perm[NMAX];          // nodes sorted by degree
__device__ int     g_viol[2];
__device__ int     g_maskmode;

__device__ __forceinline__ float gelu_f(float x) {
    return 0.5f * x * (1.0f + erff(x * 0.7071067811865476f));
}
__device__ __forceinline__ __half2 h2bits(unsigned u) { return *(__half2*)&u; }

// ---------------- CSR count + mask detect + weight fp16 conversion ----------------
__global__ void k_count(const int* ei, const int* m,
                        const float* __restrict__ Wl, const float* __restrict__ Wr,
                        int e, int n) {
    int i = blockIdx.x * blockDim.x + threadIdx.x;
    if (i < e) atomicAdd(&g_cnt[ei[e + i]], 1);
    int words = n >> 2;
    int lim = words < 8192 ? words : 8192;
    if (i < lim) {
        int v = m[i];
        if (v != 0 && v != 1) atomicOr(&g_viol[0], 1);
        if (v != 0 && v != 0x3F800000) atomicOr(&g_viol[1], 1);
    }
    if (i < 4 * 32768) {
        int l = i >> 15, rem = i & 32767;
        int nn = rem & 255, kk = rem >> 8;
        float v = (nn < 128) ? Wl[l * 16384 + kk * 128 + nn]
                             : Wr[l * 16384 + kk * 128 + nn - 128];
        g_Wh[(l << 15) + nn * 128 + kk] = __float2half_rn(v);
    }
}

// ---------------- merged: block 0 = scan + degree sort, blocks 1.. = prep ----------------
__global__ void k_scan_prep(const float* __restrict__ x, const float* __restrict__ tmp,
                            const float* __restrict__ encW, const float* __restrict__ encB,
                            const float* __restrict__ encG, const float* __restrict__ encBe,
                            const float* __restrict__ fW1, const float* __restrict__ fb1,
                            const float* __restrict__ fW2, const float* __restrict__ fb2,
                            int n) {
    int tid = threadIdx.x;
    if (blockIdx.x == 0) {
        __shared__ int warpsum[32];
        __shared__ int hist[512];
        __shared__ int basebin[512];
        int t = tid;
        int per = (n + 1023) >> 10;
        int i0 = t * per;
        int i1 = i0 + per; if (i1 > n) i1 = n; if (i0 > n) i0 = n;
        int local = 0;
        for (int i = i0; i < i1; i++) local += g_cnt[i];
        int lane = t & 31, warp = t >> 5;
        int v = local;
        #pragma unroll
        for (int o = 1; o < 32; o <<= 1) {
            int u = __shfl_up_sync(0xFFFFFFFFu, v, o);
            if (lane >= o) v += u;
        }
        if (lane == 31) warpsum[warp] = v;
        __syncthreads();
        if (warp == 0) {
            int w = warpsum[lane];
            #pragma unroll
            for (int o = 1; o < 32; o <<= 1) {
                int u = __shfl_up_sync(0xFFFFFFFFu, w, o);
                if (lane >= o) w += u;
            }
            warpsum[lane] = w;
        }
        __syncthreads();
        int excl = v - local + (warp ? warpsum[warp - 1] : 0);
        int run = excl;
        for (int i = i0; i < i1; i++) {
            int c = g_cnt[i];
            g_off[i] = run;
            g_cnt[i] = run;
            run += c;
        }
        if (t == 1023) g_off[n] = run;
        if (t == 0) g_maskmode = (g_viol[0] == 0) ? 0 : ((g_viol[1] == 0) ? 1 : 2);

        // ---- degree-sort permutation (counting sort, 512 bins) ----
        for (int k = tid; k < 512; k += 1024) hist[k] = 0;
        __syncthreads();
        for (int i = i0; i < i1; i++) {
            int d = g_off[i + 1] - g_off[i];
            if (d > 511) d = 511;
            atomicAdd(&hist[d], 1);
        }
        __syncthreads();
        int hv = 0, hincl = 0;
        if (tid < 512) {
            hv = hist[tid];
            hincl = hv;
            #pragma unroll
            for (int o = 1; o < 32; o <<= 1) {
                int u = __shfl_up_sync(0xFFFFFFFFu, hincl, o);
                if (lane >= o) hincl += u;
            }
            if (lane == 31) warpsum[warp] = hincl;
        }
        __syncthreads();
        if (warp == 0 && lane < 16) {
            int w = warpsum[lane];
            #pragma unroll
            for (int o = 1; o < 16; o <<= 1) {
                int u = __shfl_up_sync(0x0000FFFFu, w, o);
                if (lane >= o) w += u;
            }
            warpsum[lane] = w;
        }
        __syncthreads();
        if (tid < 512) {
            basebin[tid] = hincl - hv + (warp ? warpsum[warp - 1] : 0);
            hist[tid] = 0;
        }
        __syncthreads();
        for (int i = i0; i < i1; i++) {
            int d = g_off[i + 1] - g_off[i];
            if (d > 511) d = 511;
            int pos = basebin[d] + atomicAdd(&hist[d], 1);
            g_perm[pos] = i;
        }
        return;
    }
    extern __shared__ float sm[];
    float* sEncW = sm;            // 768
    float* sW1   = sm + 768;      // 64
    float* sB1   = sm + 832;      // 64
    float* sB2   = sm + 896;      // 256
    float* sW2   = sm + 1152;     // 16384
    float* sT1   = sm + 17536;    // 2048 (32 warps x 64)
    for (int i = tid; i < 768; i += blockDim.x) sEncW[i] = encW[i];
    for (int i = tid; i < 64; i += blockDim.x) { sW1[i] = fW1[i]; sB1[i] = fb1[i]; }
    for (int i = tid; i < 256; i += blockDim.x) sB2[i] = fb2[i];
    for (int i = tid; i < 4096; i += blockDim.x)
        ((float4*)sW2)[i] = ((const float4*)fW2)[i];
    __syncthreads();
    int warp = tid >> 5, lane = tid & 31;
    int nb = gridDim.x - 1, pb = blockIdx.x - 1;
    for (int i = pb * 32 + warp; i < n; i += nb * 32) {
        float xv[6];
        #pragma unroll
        for (int j = 0; j < 6; j++) xv[j] = x[i * 6 + j];
        float y[4];
        #pragma unroll
        for (int h = 0; h < 4; h++) {
            int k = h * 32 + lane;
            float a = encB[k];
            #pragma unroll
            for (int j = 0; j < 6; j++) a += xv[j] * sEncW[j * 128 + k];
            y[h] = a;
        }
        float s1 = y[0] + y[1] + y[2] + y[3];
        float s2 = y[0]*y[0] + y[1]*y[1] + y[2]*y[2] + y[3]*y[3];
        #pragma unroll
        for (int o = 16; o > 0; o >>= 1) {
            s1 += __shfl_xor_sync(0xFFFFFFFFu, s1, o);
            s2 += __shfl_xor_sync(0xFFFFFFFFu, s2, o);
        }
        float mean = s1 * (1.0f / 128.0f);
        float var  = s2 * (1.0f / 128.0f) - mean * mean;
        float inv  = rsqrtf(var + 1e-5f);
        #pragma unroll
        for (int h = 0; h < 4; h++) {
            int k = h * 32 + lane;
            float v = (y[h] - mean) * inv * encG[k] + encBe[k];
            g_hh[i * 128 + k] = __float2half_rn(gelu_f(v));
        }
        float tm = tmp[i];
        #pragma unroll
        for (int c = 0; c < 2; c++) {
            int j = lane + 32 * c;
            sT1[warp * 64 + j] = gelu_f(tm * sW1[j] + sB1[j]);
        }
        __syncwarp();
        float f[8];
        #pragma unroll
        for (int c = 0; c < 8; c++) f[c] = sB2[lane + 32 * c];
        for (int j = 0; j < 64; j++) {
            float t = sT1[warp * 64 + j];
            #pragma unroll
            for (int c = 0; c < 8; c++) f[c] += t * sW2[j * 256 + lane + 32 * c];
        }
        #pragma unroll
        for (int c = 0; c < 4; c++) {
            g_gamma[i * 128 + lane + 32 * c] = f[c];
            g_beta[i * 128 + lane + 32 * c]  = f[c + 4];
        }
        __syncwarp();
    }
}

// ---------------- tensor-core half-GEMM body ----------------
#define AST 136   // padded k-stride (halfs)
__device__ __forceinline__ void gemm_body(
    const __half* __restrict__ Wh, const float* __restrict__ bias,
    int n, int row0, int which, __half* smh, int tid) {
    __half* As = smh;               // 128 x 136
    __half* Bs = smh + 128 * AST;   // 128 x 136

    for (int idx = tid; idx < 2048; idx += 512) {
        int row = idx >> 4, c8 = idx & 15;
        int gr = row0 + row;
        uint4 v = make_uint4(0, 0, 0, 0);
        if (gr < n) v = ((const uint4*)g_hh)[gr * 16 + c8];
        *(uint4*)&As[row * AST + c8 * 8] = v;
    }
    const __half* Wsel = Wh + which * 16384;
    for (int idx = tid; idx < 2048; idx += 512) {
        int nn = idx >> 4, c8 = idx & 15;
        uint4 v = ((const uint4*)(Wsel + nn * 128))[c8];
        *(uint4*)&Bs[nn * AST + c8 * 8] = v;
    }
    __syncthreads();

    int warp = tid >> 5, lane = tid & 31;
    int mi = warp & 3, ni = warp >> 2;
    int gid = lane >> 2, tig = lane & 3;

    float d[2][4][4];
    #pragma unroll
    for (int tm = 0; tm < 2; tm++)
        #pragma unroll
        for (int tn = 0; tn < 4; tn++)
            #pragma unroll
            for (int q = 0; q < 4; q++) d[tm][tn][q] = 0.f;

    #pragma unroll
    for (int ks = 0; ks < 8; ks++) {
        int k0 = ks * 16;
        unsigned a[2][4];
        #pragma unroll
        for (int tm = 0; tm < 2; tm++) {
            int r = mi * 32 + tm * 16 + gid;
            a[tm][0] = *(const unsigned*)&As[r * AST + k0 + tig * 2];
            a[tm][1] = *(const unsigned*)&As[(r + 8) * AST + k0 + tig * 2];
            a[tm][2] = *(const unsigned*)&As[r * AST + k0 + tig * 2 + 8];
            a[tm][3] = *(const unsigned*)&As[(r + 8) * AST + k0 + tig * 2 + 8];
        }
        unsigned b[4][2];
        #pragma unroll
        for (int tn = 0; tn < 4; tn++) {
            int nn = ni * 32 + tn * 8 + gid;
            b[tn][0] = *(const unsigned*)&Bs[nn * AST + k0 + tig * 2];
            b[tn][1] = *(const unsigned*)&Bs[nn * AST + k0 + tig * 2 + 8];
        }
        #pragma unroll
        for (int tm = 0; tm < 2; tm++)
            #pragma unroll
            for (int tn = 0; tn < 4; tn++) {
                asm volatile(
                    "mma.sync.aligned.m16n8k16.row.col.f32.f16.f16.f32 "
                    "{%0,%1,%2,%3}, {%4,%5,%6,%7}, {%8,%9}, {%0,%1,%2,%3};\n"
                    : "+f"(d[tm][tn][0]), "+f"(d[tm][tn][1]),
                      "+f"(d[tm][tn][2]), "+f"(d[tm][tn][3])
                    : "r"(a[tm][0]), "r"(a[tm][1]), "r"(a[tm][2]), "r"(a[tm][3]),
                      "r"(b[tn][0]), "r"(b[tn][1]));
            }
    }

    __half2* dst = which ? g_xrh : g_xlh;
    #pragma unroll
    for (int tn = 0; tn < 4; tn++) {
        int nglob = ni * 32 + tn * 8 + tig * 2;   // 0..127
        float b0 = bias[nglob], b1 = bias[nglob + 1];
        #pragma unroll
        for (int tm = 0; tm < 2; tm++) {
            int r0 = row0 + mi * 32 + tm * 16 + gid;
            int r1 = r0 + 8;
            float v0 = d[tm][tn][0] + b0, v1 = d[tm][tn][1] + b1;
            float v2 = d[tm][tn][2] + b0, v3 = d[tm][tn][3] + b1;
            int c = nglob >> 1;
            if (r0 < n) dst[r0 * 64 + c] = __floats2half2_rn(v0, v1);
            if (r1 < n) dst[r1 * 64 + c] = __floats2half2_rn(v2, v3);
        }
    }
}

__global__ void __launch_bounds__(512, 2)
k_gemm(const __half* __restrict__ Wh, const float* __restrict__ blv,
       const float* __restrict__ brv, int n) {
    extern __shared__ __half smh[];
    int which = blockIdx.x & 1;
    gemm_body(Wh, which ? brv : blv, n, (blockIdx.x >> 1) * 128, which,
              smh, threadIdx.x);
}

// merged: gemm blocks [0, gB) + scatter blocks [gB, ...)
__global__ void __launch_bounds__(512, 2)
k_scatter_gemm(const __half* __restrict__ Wh, const float* __restrict__ blv,
               const float* __restrict__ brv,
               const int* ei, const float4* __restrict__ ea, int e, int n, int gB) {
    extern __shared__ __half smh[];
    if ((int)blockIdx.x < gB) {
        int which = blockIdx.x & 1;
        gemm_body(Wh, which ? brv : blv, n, (blockIdx.x >> 1) * 128, which,
                  smh, threadIdx.x);
        return;
    }
    int base = (blockIdx.x - gB) * 1024 + threadIdx.x;
    #pragma unroll
    for (int k = 0; k < 2; k++) {
        int idx = base + k * 512;
        if (idx < e) {
            int s = ei[idx], d = ei[e + idx];
            int pos = atomicAdd(&g_cnt[d], 1);
            g_csrc[pos] = s;
            float4 a = ea[idx];
            __half2 h0 = __floats2half2_rn(a.x, a.y);
            __half2 h1 = __floats2half2_rn(a.z, a.w);
            g_eah[pos] = make_uint2(*(unsigned*)&h0, *(unsigned*)&h1);
        }
    }
}

// ---- fused edge+softmax+aggregate+FiLM+LN+GELU+residual ----
// R11 inner loop (frozen, 48-reg optimum); fp16 residual h; degree-sorted scheduling
__global__ void k_node(const float* __restrict__ We, const float* __restrict__ att,
                       const float* __restrict__ cb, const float* __restrict__ lng,
                       const float* __restrict__ lnb, int n) {
    int tid = threadIdx.x;
    int warp = tid >> 5, lane = tid & 31;
    int idx = blockIdx.x * 8 + warp;
    if (idx >= n) return;
    int i = g_perm[idx];

    float4 wf0 = ((const float4*)We)[lane];
    float4 wf1 = ((const float4*)We)[32 + lane];
    float4 wf2 = ((const float4*)We)[64 + lane];
    float4 wf3 = ((const float4*)We)[96 + lane];
    __half2 w0a = __floats2half2_rn(wf0.x, wf0.y), w0b = __floats2half2_rn(wf0.z, wf0.w);
    __half2 w1a = __floats2half2_rn(wf1.x, wf1.y), w1b = __floats2half2_rn(wf1.z, wf1.w);
    __half2 w2a = __floats2half2_rn(wf2.x, wf2.y), w2b = __floats2half2_rn(wf2.z, wf2.w);
    __half2 w3a = __floats2half2_rn(wf3.x, wf3.y), w3b = __floats2half2_rn(wf3.z, wf3.w);
    float4 atf = ((const float4*)att)[lane];
    __half2 at01 = __floats2half2_rn(atf.x, atf.y), at23 = __floats2half2_rn(atf.z, atf.w);
    uint2 xrr = ((const uint2*)g_xrh)[i * 32 + lane];
    __half2 xr01 = h2bits(xrr.x), xr23 = h2bits(xrr.y);
    const __half2 c02 = __float2half2_rn(0.2f);

    int beg = g_off[i], end = g_off[i + 1];
    float sme = 0.f;
    float4 acc = make_float4(0.f, 0.f, 0.f, 0.f);
    const uint2* xlh = (const uint2*)g_xlh;

    for (int j = beg; j < end; j += 4) {
        int c = end - j;
        int s0 = g_csrc[j];
        int s1 = (c > 1) ? g_csrc[j + 1] : s0;
        int s2 = (c > 2) ? g_csrc[j + 2] : s0;
        int s3 = (c > 3) ? g_csrc[j + 3] : s0;
        uint2 e0 = g_eah[j];
        uint2 e1 = (c > 1) ? g_eah[j + 1] : e0;
        uint2 e2 = (c > 2) ? g_eah[j + 2] : e0;
        uint2 e3 = (c > 3) ? g_eah[j + 3] : e0;
        uint2 r0 = xlh[s0 * 32 + lane];
        uint2 r1 = xlh[s1 * 32 + lane];
        uint2 r2 = xlh[s2 * 32 + lane];
        uint2 r3 = xlh[s3 * 32 + lane];

        float2 xa0, xb0, xa1, xb1, xa2, xb2, xa3, xb3;
        float p0, p1, p2, p3;
        #define EDGE_H2(rr, ed, xa, xb, pp)                                      \
        {                                                                        \
            __half2 xl01 = h2bits(rr.x), xl23 = h2bits(rr.y);                    \
            __half2 ex = h2bits(ed.x), ey = h2bits(ed.y);                        \
            __half2 b0 = __low2half2(ex), b1 = __high2half2(ex);                 \
            __half2 b2 = __low2half2(ey), b3 = __high2half2(ey);                 \
            __half2 m01 = __hadd2(xl01, xr01);                                   \
            m01 = __hfma2(b0, w0a, m01); m01 = __hfma2(b1, w1a, m01);            \
            m01 = __hfma2(b2, w2a, m01); m01 = __hfma2(b3, w3a, m01);            \
            __half2 m23 = __hadd2(xl23, xr23);                                   \
            m23 = __hfma2(b0, w0b, m23); m23 = __hfma2(b1, w1b, m23);            \
            m23 = __hfma2(b2, w2b, m23); m23 = __hfma2(b3, w3b, m23);            \
            m01 = __hmax2(m01, __hmul2(m01, c02));                               \
            m23 = __hmax2(m23, __hmul2(m23, c02));                               \
            __half2 pr = __hmul2(m01, at01);                                     \
            pr = __hfma2(m23, at23, pr);                                         \
            float2 pf = __half22float2(pr);                                      \
            pp = pf.x + pf.y;                                                    \
            xa = __half22float2(xl01);                                           \
            xb = __half22float2(xl23);                                           \
        }
        EDGE_H2(r0, e0, xa0, xb0, p0)
        EDGE_H2(r1, e1, xa1, xb1, p1)
        EDGE_H2(r2, e2, xa2, xb2, p2)
        EDGE_H2(r3, e3, xa3, xb3, p3)
        #undef EDGE_H2

        #pragma unroll
        for (int o = 1; o < 8; o <<= 1) {
            p0 += __shfl_xor_sync(0xFFFFFFFFu, p0, o);
            p1 += __shfl_xor_sync(0xFFFFFFFFu, p1, o);
            p2 += __shfl_xor_sync(0xFFFFFFFFu, p2, o);
            p3 += __shfl_xor_sync(0xFFFFFFFFu, p3, o);
        }
        float w0 = __expf(p0);
        float w1 = (c > 1) ? __expf(p1) : 0.f;
        float w2 = (c > 2) ? __expf(p2) : 0.f;
        float w3 = (c > 3) ? __expf(p3) : 0.f;
        sme += (w0 + w1) + (w2 + w3);
        acc.x += w0*xa0.x + w1*xa1.x + w2*xa2.x + w3*xa3.x;
        acc.y += w0*xa0.y + w1*xa1.y + w2*xa2.y + w3*xa3.y;
        acc.z += w0*xb0.x + w1*xb1.x + w2*xb2.x + w3*xb3.x;
        acc.w += w0*xb0.y + w1*xb1.y + w2*xb2.y + w3*xb3.y;
    }

    float inv = 1.0f / (sme + 1e-16f);
    float4 cb4 = ((const float4*)cb)[lane];
    float4 ga  = ((const float4*)g_gamma)[i * 32 + lane];
    float4 be  = ((const float4*)g_beta)[i * 32 + lane];
    float y0 = ga.x * (acc.x * inv + cb4.x) + be.x;
    float y1 = ga.y * (acc.y * inv + cb4.y) + be.y;
    float y2 = ga.z * (acc.z * inv + cb4.z) + be.z;
    float y3 = ga.w * (acc.w * inv + cb4.w) + be.w;
    float s1 = y0 + y1 + y2 + y3;
    float s2 = y0*y0 + y1*y1 + y2*y2 + y3*y3;
    #pragma unroll
    for (int o = 16; o > 0; o >>= 1) {
        s1 += __shfl_xor_sync(0xFFFFFFFFu, s1, o);
        s2 += __shfl_xor_sync(0xFFFFFFFFu, s2, o);
    }
    float mean = s1 * (1.0f / 128.0f);
    float var  = s2 * (1.0f / 128.0f) - mean * mean;
    float ivs  = rsqrtf(var + 1e-5f);
    float4 g4 = ((const float4*)lng)[lane];
    float4 b4 = ((const float4*)lnb)[lane];
    uint2 hraw = ((const uint2*)g_hh)[i * 32 + lane];
    float2 h01 = __half22float2(h2bits(hraw.x));
    float2 h23 = __half22float2(h2bits(hraw.y));
    float o0 = gelu_f((y0 - mean) * ivs * g4.x + b4.x) + h01.x;
    float o1 = gelu_f((y1 - mean) * ivs * g4.y + b4.y) + h01.y;
    float o2 = gelu_f((y2 - mean) * ivs * g4.z + b4.z) + h23.x;
    float o3 = gelu_f((y3 - mean) * ivs * g4.w + b4.w) + h23.y;
    __half2 q0 = __floats2half2_rn(o0, o1);
    __half2 q1 = __floats2half2_rn(o2, o3);
    uint2 pk;
    pk.x = *(unsigned*)&q0;
    pk.y = *(unsigned*)&q1;
    ((uint2*)g_hh)[i * 32 + lane] = pk;
}

// ---------------- decoder + mask + output (+ reset counters) ----------------
__global__ void k_dec(const float* __restrict__ W1, const float* __restrict__ b1,
                      const float* __restrict__ W2, const float* __restrict__ b2,
                      const float* __restrict__ x, const void* __restrict__ mask,
                      float* __restrict__ out, int n, int out_size) {
    __shared__ float sW1[8192];
    __shared__ float sW2[128];
    __shared__ float sb1v[64];
    __shared__ float sb2v[2];
    __shared__ float sH[8][128];
    int tid = threadIdx.x;
    for (int g = blockIdx.x * blockDim.x + tid; g < n; g += gridDim.x * blockDim.x)
        g_cnt[g] = 0;
    if (blockIdx.x == 0 && tid < 2) g_viol[tid] = 0;
    for (int i = tid; i < 8192; i += 256) sW1[i] = W1[i];
    if (tid < 128) sW2[tid] = W2[tid];
    if (tid < 64) sb1v[tid] = b1[tid];
    if (tid < 2) sb2v[tid] = b2[tid];
    __syncthreads();
    int warp = tid >> 5, lane = tid & 31;
    int mode = g_maskmode;
    for (int i = blockIdx.x * 8 + warp; i < n; i += gridDim.x * 8) {
        // h in fp16: load 4 uint2 per lane-quarter
        #pragma unroll
        for (int h = 0; h < 4; h++) {
            uint2 hv = ((const uint2*)g_hh)[i * 32 + h * 8 + (lane >> 2)];
            if ((lane & 3) == 0) {
                float2 a = __half22float2(h2bits(hv.x));
                float2 b = __half22float2(h2bits(hv.y));
                int base = h * 32 + (lane >> 2) * 4;
                sH[warp][base]     = a.x;
                sH[warp][base + 1] = a.y;
                sH[warp][base + 2] = b.x;
                sH[warp][base + 3] = b.y;
            }
        }
        __syncwarp();
        float a0 = sb1v[lane], a1 = sb1v[lane + 32];
        for (int k = 0; k < 128; k++) {
            float hv = sH[warp][k];
            a0 += hv * sW1[k * 64 + lane];
            a1 += hv * sW1[k * 64 + lane + 32];
        }
        float t0 = gelu_f(a0), t1 = gelu_f(a1);
        float d0 = t0 * sW2[lane * 2]     + t1 * sW2[(lane + 32) * 2];
        float d1 = t0 * sW2[lane * 2 + 1] + t1 * sW2[(lane + 32) * 2 + 1];
        #pragma unroll
        for (int o = 16; o > 0; o >>= 1) {
            d0 += __shfl_xor_sync(0xFFFFFFFFu, d0, o);
            d1 += __shfl_xor_sync(0xFFFFFFFFu, d1, o);
        }
        if (lane == 0) {
            d0 += sb2v[0]; d1 += sb2v[1];
            int fixed;
            if (mode == 0)      fixed = ((const int*)mask)[i] != 0;
            else if (mode == 1) fixed = ((const float*)mask)[i] != 0.f;
            else                fixed = ((const unsigned char*)mask)[i] != 0;
            if (fixed) { d0 = 0.f; d1 = 0.f; }
            out[i * 2]     = x[i * 6]     + d0;
            out[i * 2 + 1] = x[i * 6 + 1] + d1;
            if (out_size >= 4 * n) {
                out[2 * n + i * 2]     = d0;
                out[2 * n + i * 2 + 1] = d1;
            }
        }
        __syncwarp();
    }
}

// ---------------- launch ----------------
extern "C" void kernel_launch(void* const* d_in, const int* in_sizes, int n_in,
                              void* d_out, int out_size) {
    const float* x    = (const float*)d_in[0];
    const int*   ei   = (const int*)d_in[1];
    const float* ea   = (const float*)d_in[2];
    const float* tmp  = (const float*)d_in[3];
    const void*  mask = d_in[4];
    const float* encW = (const float*)d_in[5];
    const float* encB = (const float*)d_in[6];
    const float* encG = (const float*)d_in[7];
    const float* encBe= (const float*)d_in[8];
    const float* fW1  = (const float*)d_in[9];
    const float* fb1  = (const float*)d_in[10];
    const float* fW2  = (const float*)d_in[11];
    const float* fb2  = (const float*)d_in[12];
    const float* Wl   = (const float*)d_in[13];
    const float* bl   = (const float*)d_in[14];
    const float* Wr   = (const float*)d_in[15];
    const float* br   = (const float*)d_in[16];
    const float* We   = (const float*)d_in[17];
    const float* att  = (const float*)d_in[18];
    const float* cb   = (const float*)d_in[19];
    const float* lng  = (const float*)d_in[20];
    const float* lnb  = (const float*)d_in[21];
    const float* dW1  = (const float*)d_in[22];
    const float* db1  = (const float*)d_in[23];
    const float* dW2  = (const float*)d_in[24];
    const float* db2  = (const float*)d_in[25];
    float* out = (float*)d_out;

    int n = in_sizes[0] / 6;
    int e = in_sizes[2] / 4;

    const int gemm_smem = 256 * AST * 2;                // 69632
    const int prep_smem = (17536 + 2048) * 4;           // 78336
    cudaFuncSetAttribute(k_scan_prep, cudaFuncAttributeMaxDynamicSharedMemorySize, prep_smem);
    cudaFuncSetAttribute(k_gemm, cudaFuncAttributeMaxDynamicSharedMemorySize, gemm_smem);
    cudaFuncSetAttribute(k_scatter_gemm, cudaFuncAttributeMaxDynamicSharedMemorySize, gemm_smem);

    int gB = 2 * ((n + 127) / 128);     // 2 half-gemm blocks per 128-row tile
    int sB = (e + 1023) / 1024;

    __half* Wh = nullptr;
    cudaGetSymbolAddress((void**)&Wh, g_Wh);

    // launches: count(0), scan_prep(1), scatter_gemm0(2), node0(3) <- profiled
    k_count<<<(e + 255) / 256, 256>>>(ei, (const int*)mask, Wl, Wr, e, n);
    k_scan_prep<<<201, 1024, prep_smem>>>(x, tmp, encW, encB, encG, encBe,
                                          fW1, fb1, fW2, fb2, n);
    k_scatter_gemm<<<gB + sB, 512, gemm_smem>>>(Wh, bl, br,
                                                ei, (const float4*)ea, e, n, gB);
    k_node<<<(n + 7) / 8, 256>>>(We, att, cb, lng, lnb, n);

    for (int l = 1; l < 4; l++) {
        k_gemm<<<gB, 512, gemm_smem>>>(Wh + l * 32768, bl + l * 128,
                                       br + l * 128, n);
        k_node<<<(n + 7) / 8, 256>>>(We + l * 512, att + l * 128,
                                     cb + l * 128, lng + l * 128, lnb + l * 128, n);
    }

    k_dec<<<296, 256>>>(dW1, db1, dW2, db2, x, mask, out, n, out_size);
}

// round 17
// speedup vs baseline: 1.0844x; 1.0085x over previous
#include <cuda_runtime.h>
#include <cuda_fp16.h>
#include <math.h>

#define HID 128
#define NMAX 50048
#define EMAX 1600000

// ---------------- device scratch ----------------
__device__ __half  g_hh[NMAX * HID];      // h in fp16 (residual + GEMM input + decoder)
__device__ __half2 g_xlh[NMAX * 64];      // xl fp16 (gather payload)
__device__ __half2 g_xrh[NMAX * 64];      // xr fp16
__device__ __half  g_gammah[NMAX * HID];  // FiLM gamma fp16
__device__ __half  g_betah[NMAX * HID];   // FiLM beta fp16
__device__ uint2   g_eah[EMAX];           // edge_attr fp16 x4, CSR-permuted
__device__ __half  g_Wh[4 * 256 * 128];   // [layer][n:256][k:128] fp16 weights
__device__ int     g_off[NMAX + 1];
__device__ int     g_cnt[NMAX];           // zero-init at load; re-zeroed by k_dec
__device__ int     g_csrc[EMAX];
__device__ int     g_perm[NMAX];          // nodes sorted by degree
__device__ int     g_viol[2];
__device__ int     g_maskmode;

__device__ __forceinline__ float gelu_f(float x) {
    return 0.5f * x * (1.0f + erff(x * 0.7071067811865476f));
}
__device__ __forceinline__ __half2 h2bits(unsigned u) { return *(__half2*)&u; }

// ---------------- CSR count + mask detect + weight fp16 conversion ----------------
__global__ void k_count(const int* ei, const int* m,
                        const float* __restrict__ Wl, const float* __restrict__ Wr,
                        int e, int n) {
    int i = blockIdx.x * blockDim.x + threadIdx.x;
    if (i < e) atomicAdd(&g_cnt[ei[e + i]], 1);
    int words = n >> 2;
    int lim = words < 8192 ? words : 8192;
    if (i < lim) {
        int v = m[i];
        if (v != 0 && v != 1) atomicOr(&g_viol[0], 1);
        if (v != 0 && v != 0x3F800000) atomicOr(&g_viol[1], 1);
    }
    if (i < 4 * 32768) {
        int l = i >> 15, rem = i & 32767;
        int nn = rem & 255, kk = rem >> 8;
        float v = (nn < 128) ? Wl[l * 16384 + kk * 128 + nn]
                             : Wr[l * 16384 + kk * 128 + nn - 128];
        g_Wh[(l << 15) + nn * 128 + kk] = __float2half_rn(v);
    }
}

// ---------------- merged: block 0 = scan + degree sort, blocks 1.. = prep ----------------
__global__ void k_scan_prep(const float* __restrict__ x, const float* __restrict__ tmp,
                            const float* __restrict__ encW, const float* __restrict__ encB,
                            const float* __restrict__ encG, const float* __restrict__ encBe,
                            const float* __restrict__ fW1, const float* __restrict__ fb1,
                            const float* __restrict__ fW2, const float* __restrict__ fb2,
                            int n) {
    int tid = threadIdx.x;
    if (blockIdx.x == 0) {
        __shared__ int warpsum[32];
        __shared__ int hist[512];
        __shared__ int basebin[512];
        int t = tid;
        int per = (n + 1023) >> 10;
        int i0 = t * per;
        int i1 = i0 + per; if (i1 > n) i1 = n; if (i0 > n) i0 = n;
        int local = 0;
        for (int i = i0; i < i1; i++) local += g_cnt[i];
        int lane = t & 31, warp = t >> 5;
        int v = local;
        #pragma unroll
        for (int o = 1; o < 32; o <<= 1) {
            int u = __shfl_up_sync(0xFFFFFFFFu, v, o);
            if (lane >= o) v += u;
        }
        if (lane == 31) warpsum[warp] = v;
        __syncthreads();
        if (warp == 0) {
            int w = warpsum[lane];
            #pragma unroll
            for (int o = 1; o < 32; o <<= 1) {
                int u = __shfl_up_sync(0xFFFFFFFFu, w, o);
                if (lane >= o) w += u;
            }
            warpsum[lane] = w;
        }
        __syncthreads();
        int excl = v - local + (warp ? warpsum[warp - 1] : 0);
        int run = excl;
        for (int i = i0; i < i1; i++) {
            int c = g_cnt[i];
            g_off[i] = run;
            g_cnt[i] = run;
            run += c;
        }
        if (t == 1023) g_off[n] = run;
        if (t == 0) g_maskmode = (g_viol[0] == 0) ? 0 : ((g_viol[1] == 0) ? 1 : 2);

        // ---- degree-sort permutation (counting sort, 512 bins) ----
        for (int k = tid; k < 512; k += 1024) hist[k] = 0;
        __syncthreads();
        for (int i = i0; i < i1; i++) {
            int d = g_off[i + 1] - g_off[i];
            if (d > 511) d = 511;
            atomicAdd(&hist[d], 1);
        }
        __syncthreads();
        int hv = 0, hincl = 0;
        if (tid < 512) {
            hv = hist[tid];
            hincl = hv;
            #pragma unroll
            for (int o = 1; o < 32; o <<= 1) {
                int u = __shfl_up_sync(0xFFFFFFFFu, hincl, o);
                if (lane >= o) hincl += u;
            }
            if (lane == 31) warpsum[warp] = hincl;
        }
        __syncthreads();
        if (warp == 0 && lane < 16) {
            int w = warpsum[lane];
            #pragma unroll
            for (int o = 1; o < 16; o <<= 1) {
                int u = __shfl_up_sync(0x0000FFFFu, w, o);
                if (lane >= o) w += u;
            }
            warpsum[lane] = w;
        }
        __syncthreads();
        if (tid < 512) {
            basebin[tid] = hincl - hv + (warp ? warpsum[warp - 1] : 0);
            hist[tid] = 0;
        }
        __syncthreads();
        for (int i = i0; i < i1; i++) {
            int d = g_off[i + 1] - g_off[i];
            if (d > 511) d = 511;
            int pos = basebin[d] + atomicAdd(&hist[d], 1);
            g_perm[pos] = i;
        }
        return;
    }
    extern __shared__ float sm[];
    float* sEncW = sm;            // 768
    float* sW1   = sm + 768;      // 64
    float* sB1   = sm + 832;      // 64
    float* sB2   = sm + 896;      // 256
    float* sW2   = sm + 1152;     // 16384
    float* sT1   = sm + 17536;    // 2048 (32 warps x 64)
    for (int i = tid; i < 768; i += blockDim.x) sEncW[i] = encW[i];
    for (int i = tid; i < 64; i += blockDim.x) { sW1[i] = fW1[i]; sB1[i] = fb1[i]; }
    for (int i = tid; i < 256; i += blockDim.x) sB2[i] = fb2[i];
    for (int i = tid; i < 4096; i += blockDim.x)
        ((float4*)sW2)[i] = ((const float4*)fW2)[i];
    __syncthreads();
    int warp = tid >> 5, lane = tid & 31;
    int nb = gridDim.x - 1, pb = blockIdx.x - 1;
    for (int i = pb * 32 + warp; i < n; i += nb * 32) {
        float xv[6];
        #pragma unroll
        for (int j = 0; j < 6; j++) xv[j] = x[i * 6 + j];
        float y[4];
        #pragma unroll
        for (int h = 0; h < 4; h++) {
            int k = h * 32 + lane;
            float a = encB[k];
            #pragma unroll
            for (int j = 0; j < 6; j++) a += xv[j] * sEncW[j * 128 + k];
            y[h] = a;
        }
        float s1 = y[0] + y[1] + y[2] + y[3];
        float s2 = y[0]*y[0] + y[1]*y[1] + y[2]*y[2] + y[3]*y[3];
        #pragma unroll
        for (int o = 16; o > 0; o >>= 1) {
            s1 += __shfl_xor_sync(0xFFFFFFFFu, s1, o);
            s2 += __shfl_xor_sync(0xFFFFFFFFu, s2, o);
        }
        float mean = s1 * (1.0f / 128.0f);
        float var  = s2 * (1.0f / 128.0f) - mean * mean;
        float inv  = rsqrtf(var + 1e-5f);
        #pragma unroll
        for (int h = 0; h < 4; h++) {
            int k = h * 32 + lane;
            float v = (y[h] - mean) * inv * encG[k] + encBe[k];
            g_hh[i * 128 + k] = __float2half_rn(gelu_f(v));
        }
        float tm = tmp[i];
        #pragma unroll
        for (int c = 0; c < 2; c++) {
            int j = lane + 32 * c;
            sT1[warp * 64 + j] = gelu_f(tm * sW1[j] + sB1[j]);
        }
        __syncwarp();
        float f[8];
        #pragma unroll
        for (int c = 0; c < 8; c++) f[c] = sB2[lane + 32 * c];
        for (int j = 0; j < 64; j++) {
            float t = sT1[warp * 64 + j];
            #pragma unroll
            for (int c = 0; c < 8; c++) f[c] += t * sW2[j * 256 + lane + 32 * c];
        }
        #pragma unroll
        for (int c = 0; c < 4; c++) {
            g_gammah[i * 128 + lane + 32 * c] = __float2half_rn(f[c]);
            g_betah[i * 128 + lane + 32 * c]  = __float2half_rn(f[c + 4]);
        }
        __syncwarp();
    }
}

// ---------------- tensor-core half-GEMM body ----------------
#define AST 136   // padded k-stride (halfs)
__device__ __forceinline__ void gemm_body(
    const __half* __restrict__ Wh, const float* __restrict__ bias,
    int n, int row0, int which, __half* smh, int tid) {
    __half* As = smh;               // 128 x 136
    __half* Bs = smh + 128 * AST;   // 128 x 136

    for (int idx = tid; idx < 2048; idx += 512) {
        int row = idx >> 4, c8 = idx & 15;
        int gr = row0 + row;
        uint4 v = make_uint4(0, 0, 0, 0);
        if (gr < n) v = ((const uint4*)g_hh)[gr * 16 + c8];
        *(uint4*)&As[row * AST + c8 * 8] = v;
    }
    const __half* Wsel = Wh + which * 16384;
    for (int idx = tid; idx < 2048; idx += 512) {
        int nn = idx >> 4, c8 = idx & 15;
        uint4 v = ((const uint4*)(Wsel + nn * 128))[c8];
        *(uint4*)&Bs[nn * AST + c8 * 8] = v;
    }
    __syncthreads();

    int warp = tid >> 5, lane = tid & 31;
    int mi = warp & 3, ni = warp >> 2;
    int gid = lane >> 2, tig = lane & 3;

    float d[2][4][4];
    #pragma unroll
    for (int tm = 0; tm < 2; tm++)
        #pragma unroll
        for (int tn = 0; tn < 4; tn++)
            #pragma unroll
            for (int q = 0; q < 4; q++) d[tm][tn][q] = 0.f;

    #pragma unroll
    for (int ks = 0; ks < 8; ks++) {
        int k0 = ks * 16;
        unsigned a[2][4];
        #pragma unroll
        for (int tm = 0; tm < 2; tm++) {
            int r = mi * 32 + tm * 16 + gid;
            a[tm][0] = *(const unsigned*)&As[r * AST + k0 + tig * 2];
            a[tm][1] = *(const unsigned*)&As[(r + 8) * AST + k0 + tig * 2];
            a[tm][2] = *(const unsigned*)&As[r * AST + k0 + tig * 2 + 8];
            a[tm][3] = *(const unsigned*)&As[(r + 8) * AST + k0 + tig * 2 + 8];
        }
        unsigned b[4][2];
        #pragma unroll
        for (int tn = 0; tn < 4; tn++) {
            int nn = ni * 32 + tn * 8 + gid;
            b[tn][0] = *(const unsigned*)&Bs[nn * AST + k0 + tig * 2];
            b[tn][1] = *(const unsigned*)&Bs[nn * AST + k0 + tig * 2 + 8];
        }
        #pragma unroll
        for (int tm = 0; tm < 2; tm++)
            #pragma unroll
            for (int tn = 0; tn < 4; tn++) {
                asm volatile(
                    "mma.sync.aligned.m16n8k16.row.col.f32.f16.f16.f32 "
                    "{%0,%1,%2,%3}, {%4,%5,%6,%7}, {%8,%9}, {%0,%1,%2,%3};\n"
                    : "+f"(d[tm][tn][0]), "+f"(d[tm][tn][1]),
                      "+f"(d[tm][tn][2]), "+f"(d[tm][tn][3])
                    : "r"(a[tm][0]), "r"(a[tm][1]), "r"(a[tm][2]), "r"(a[tm][3]),
                      "r"(b[tn][0]), "r"(b[tn][1]));
            }
    }

    __half2* dst = which ? g_xrh : g_xlh;
    #pragma unroll
    for (int tn = 0; tn < 4; tn++) {
        int nglob = ni * 32 + tn * 8 + tig * 2;   // 0..127
        float b0 = bias[nglob], b1 = bias[nglob + 1];
        #pragma unroll
        for (int tm = 0; tm < 2; tm++) {
            int r0 = row0 + mi * 32 + tm * 16 + gid;
            int r1 = r0 + 8;
            float v0 = d[tm][tn][0] + b0, v1 = d[tm][tn][1] + b1;
            float v2 = d[tm][tn][2] + b0, v3 = d[tm][tn][3] + b1;
            int c = nglob >> 1;
            if (r0 < n) dst[r0 * 64 + c] = __floats2half2_rn(v0, v1);
            if (r1 < n) dst[r1 * 64 + c] = __floats2half2_rn(v2, v3);
        }
    }
}

__global__ void __launch_bounds__(512, 2)
k_gemm(const __half* __restrict__ Wh, const float* __restrict__ blv,
       const float* __restrict__ brv, int n) {
    extern __shared__ __half smh[];
    int which = blockIdx.x & 1;
    gemm_body(Wh, which ? brv : blv, n, (blockIdx.x >> 1) * 128, which,
              smh, threadIdx.x);
}

// merged: gemm blocks [0, gB) + scatter blocks [gB, ...)
__global__ void __launch_bounds__(512, 2)
k_scatter_gemm(const __half* __restrict__ Wh, const float* __restrict__ blv,
               const float* __restrict__ brv,
               const int* ei, const float4* __restrict__ ea, int e, int n, int gB) {
    extern __shared__ __half smh[];
    if ((int)blockIdx.x < gB) {
        int which = blockIdx.x & 1;
        gemm_body(Wh, which ? brv : blv, n, (blockIdx.x >> 1) * 128, which,
                  smh, threadIdx.x);
        return;
    }
    int base = (blockIdx.x - gB) * 1024 + threadIdx.x;
    #pragma unroll
    for (int k = 0; k < 2; k++) {
        int idx = base + k * 512;
        if (idx < e) {
            int s = ei[idx], d = ei[e + idx];
            int pos = atomicAdd(&g_cnt[d], 1);
            g_csrc[pos] = s;
            float4 a = ea[idx];
            __half2 h0 = __floats2half2_rn(a.x, a.y);
            __half2 h1 = __floats2half2_rn(a.z, a.w);
            g_eah[pos] = make_uint2(*(unsigned*)&h0, *(unsigned*)&h1);
        }
    }
}

// ---- fused edge+softmax+aggregate+FiLM+LN+GELU+residual ----
// R11 inner loop (frozen, 48-reg optimum); all node-phase streams fp16
__global__ void k_node(const float* __restrict__ We, const float* __restrict__ att,
                       const float* __restrict__ cb, const float* __restrict__ lng,
                       const float* __restrict__ lnb, int n) {
    int tid = threadIdx.x;
    int warp = tid >> 5, lane = tid & 31;
    int idx = blockIdx.x * 8 + warp;
    if (idx >= n) return;
    int i = g_perm[idx];

    float4 wf0 = ((const float4*)We)[lane];
    float4 wf1 = ((const float4*)We)[32 + lane];
    float4 wf2 = ((const float4*)We)[64 + lane];
    float4 wf3 = ((const float4*)We)[96 + lane];
    __half2 w0a = __floats2half2_rn(wf0.x, wf0.y), w0b = __floats2half2_rn(wf0.z, wf0.w);
    __half2 w1a = __floats2half2_rn(wf1.x, wf1.y), w1b = __floats2half2_rn(wf1.z, wf1.w);
    __half2 w2a = __floats2half2_rn(wf2.x, wf2.y), w2b = __floats2half2_rn(wf2.z, wf2.w);
    __half2 w3a = __floats2half2_rn(wf3.x, wf3.y), w3b = __floats2half2_rn(wf3.z, wf3.w);
    float4 atf = ((const float4*)att)[lane];
    __half2 at01 = __floats2half2_rn(atf.x, atf.y), at23 = __floats2half2_rn(atf.z, atf.w);
    uint2 xrr = ((const uint2*)g_xrh)[i * 32 + lane];
    __half2 xr01 = h2bits(xrr.x), xr23 = h2bits(xrr.y);
    const __half2 c02 = __float2half2_rn(0.2f);

    int beg = g_off[i], end = g_off[i + 1];
    float sme = 0.f;
    float4 acc = make_float4(0.f, 0.f, 0.f, 0.f);
    const uint2* xlh = (const uint2*)g_xlh;

    for (int j = beg; j < end; j += 4) {
        int c = end - j;
        int s0 = g_csrc[j];
        int s1 = (c > 1) ? g_csrc[j + 1] : s0;
        int s2 = (c > 2) ? g_csrc[j + 2] : s0;
        int s3 = (c > 3) ? g_csrc[j + 3] : s0;
        uint2 e0 = g_eah[j];
        uint2 e1 = (c > 1) ? g_eah[j + 1] : e0;
        uint2 e2 = (c > 2) ? g_eah[j + 2] : e0;
        uint2 e3 = (c > 3) ? g_eah[j + 3] : e0;
        uint2 r0 = xlh[s0 * 32 + lane];
        uint2 r1 = xlh[s1 * 32 + lane];
        uint2 r2 = xlh[s2 * 32 + lane];
        uint2 r3 = xlh[s3 * 32 + lane];

        float2 xa0, xb0, xa1, xb1, xa2, xb2, xa3, xb3;
        float p0, p1, p2, p3;
        #define EDGE_H2(rr, ed, xa, xb, pp)                                      \
        {                                                                        \
            __half2 xl01 = h2bits(rr.x), xl23 = h2bits(rr.y);                    \
            __half2 ex = h2bits(ed.x), ey = h2bits(ed.y);                        \
            __half2 b0 = __low2half2(ex), b1 = __high2half2(ex);                 \
            __half2 b2 = __low2half2(ey), b3 = __high2half2(ey);                 \
            __half2 m01 = __hadd2(xl01, xr01);                                   \
            m01 = __hfma2(b0, w0a, m01); m01 = __hfma2(b1, w1a, m01);            \
            m01 = __hfma2(b2, w2a, m01); m01 = __hfma2(b3, w3a, m01);            \
            __half2 m23 = __hadd2(xl23, xr23);                                   \
            m23 = __hfma2(b0, w0b, m23); m23 = __hfma2(b1, w1b, m23);            \
            m23 = __hfma2(b2, w2b, m23); m23 = __hfma2(b3, w3b, m23);            \
            m01 = __hmax2(m01, __hmul2(m01, c02));                               \
            m23 = __hmax2(m23, __hmul2(m23, c02));                               \
            __half2 pr = __hmul2(m01, at01);                                     \
            pr = __hfma2(m23, at23, pr);                                         \
            float2 pf = __half22float2(pr);                                      \
            pp = pf.x + pf.y;                                                    \
            xa = __half22float2(xl01);                                           \
            xb = __half22float2(xl23);                                           \
        }
        EDGE_H2(r0, e0, xa0, xb0, p0)
        EDGE_H2(r1, e1, xa1, xb1, p1)
        EDGE_H2(r2, e2, xa2, xb2, p2)
        EDGE_H2(r3, e3, xa3, xb3, p3)
        #undef EDGE_H2

        #pragma unroll
        for (int o = 1; o < 8; o <<= 1) {
            p0 += __shfl_xor_sync(0xFFFFFFFFu, p0, o);
            p1 += __shfl_xor_sync(0xFFFFFFFFu, p1, o);
            p2 += __shfl_xor_sync(0xFFFFFFFFu, p2, o);
            p3 += __shfl_xor_sync(0xFFFFFFFFu, p3, o);
        }
        float w0 = __expf(p0);
        float w1 = (c > 1) ? __expf(p1) : 0.f;
        float w2 = (c > 2) ? __expf(p2) : 0.f;
        float w3 = (c > 3) ? __expf(p3) : 0.f;
        sme += (w0 + w1) + (w2 + w3);
        acc.x += w0*xa0.x + w1*xa1.x + w2*xa2.x + w3*xa3.x;
        acc.y += w0*xa0.y + w1*xa1.y + w2*xa2.y + w3*xa3.y;
        acc.z += w0*xb0.x + w1*xb1.x + w2*xb2.x + w3*xb3.x;
        acc.w += w0*xb0.y + w1*xb1.y + w2*xb2.y + w3*xb3.y;
    }

    float inv = 1.0f / (sme + 1e-16f);
    float4 cb4 = ((const float4*)cb)[lane];
    uint2 graw = ((const uint2*)g_gammah)[i * 32 + lane];
    uint2 braw = ((const uint2*)g_betah)[i * 32 + lane];
    float2 ga01 = __half22float2(h2bits(graw.x));
    float2 ga23 = __half22float2(h2bits(graw.y));
    float2 be01 = __half22float2(h2bits(braw.x));
    float2 be23 = __half22float2(h2bits(braw.y));
    float y0 = ga01.x * (acc.x * inv + cb4.x) + be01.x;
    float y1 = ga01.y * (acc.y * inv + cb4.y) + be01.y;
    float y2 = ga23.x * (acc.z * inv + cb4.z) + be23.x;
    float y3 = ga23.y * (acc.w * inv + cb4.w) + be23.y;
    float s1 = y0 + y1 + y2 + y3;
    float s2 = y0*y0 + y1*y1 + y2*y2 + y3*y3;
    #pragma unroll
    for (int o = 16; o > 0; o >>= 1) {
        s1 += __shfl_xor_sync(0xFFFFFFFFu, s1, o);
        s2 += __shfl_xor_sync(0xFFFFFFFFu, s2, o);
    }
    float mean = s1 * (1.0f / 128.0f);
    float var  = s2 * (1.0f / 128.0f) - mean * mean;
    float ivs  = rsqrtf(var + 1e-5f);
    float4 g4 = ((const float4*)lng)[lane];
    float4 b4 = ((const float4*)lnb)[lane];
    uint2 hraw = ((const uint2*)g_hh)[i * 32 + lane];
    float2 h01 = __half22float2(h2bits(hraw.x));
    float2 h23 = __half22float2(h2bits(hraw.y));
    float o0 = gelu_f((y0 - mean) * ivs * g4.x + b4.x) + h01.x;
    float o1 = gelu_f((y1 - mean) * ivs * g4.y + b4.y) + h01.y;
    float o2 = gelu_f((y2 - mean) * ivs * g4.z + b4.z) + h23.x;
    float o3 = gelu_f((y3 - mean) * ivs * g4.w + b4.w) + h23.y;
    __half2 q0 = __floats2half2_rn(o0, o1);
    __half2 q1 = __floats2half2_rn(o2, o3);
    uint2 pk;
    pk.x = *(unsigned*)&q0;
    pk.y = *(unsigned*)&q1;
    ((uint2*)g_hh)[i * 32 + lane] = pk;
}

// ---------------- decoder + mask + output (+ reset counters) ----------------
__global__ void k_dec(const float* __restrict__ W1, const float* __restrict__ b1,
                      const float* __restrict__ W2, const float* __restrict__ b2,
                      const float* __restrict__ x, const void* __restrict__ mask,
                      float* __restrict__ out, int n, int out_size) {
    __shared__ float sW1[8192];
    __shared__ float sW2[128];
    __shared__ float sb1v[64];
    __shared__ float sb2v[2];
    __shared__ float sH[8][128];
    int tid = threadIdx.x;
    for (int g = blockIdx.x * blockDim.x + tid; g < n; g += gridDim.x * blockDim.x)
        g_cnt[g] = 0;
    if (blockIdx.x == 0 && tid < 2) g_viol[tid] = 0;
    for (int i = tid; i < 8192; i += 256) sW1[i] = W1[i];
    if (tid < 128) sW2[tid] = W2[tid];
    if (tid < 64) sb1v[tid] = b1[tid];
    if (tid < 2) sb2v[tid] = b2[tid];
    __syncthreads();
    int warp = tid >> 5, lane = tid & 31;
    int mode = g_maskmode;
    for (int i = blockIdx.x * 8 + warp; i < n; i += gridDim.x * 8) {
        #pragma unroll
        for (int h = 0; h < 4; h++) {
            uint2 hv = ((const uint2*)g_hh)[i * 32 + h * 8 + (lane >> 2)];
            if ((lane & 3) == 0) {
                float2 a = __half22float2(h2bits(hv.x));
                float2 b = __half22float2(h2bits(hv.y));
                int base = h * 32 + (lane >> 2) * 4;
                sH[warp][base]     = a.x;
                sH[warp][base + 1] = a.y;
                sH[warp][base + 2] = b.x;
                sH[warp][base + 3] = b.y;
            }
        }
        __syncwarp();
        float a0 = sb1v[lane], a1 = sb1v[lane + 32];
        for (int k = 0; k < 128; k++) {
            float hv = sH[warp][k];
            a0 += hv * sW1[k * 64 + lane];
            a1 += hv * sW1[k * 64 + lane + 32];
        }
        float t0 = gelu_f(a0), t1 = gelu_f(a1);
        float d0 = t0 * sW2[lane * 2]     + t1 * sW2[(lane + 32) * 2];
        float d1 = t0 * sW2[lane * 2 + 1] + t1 * sW2[(lane + 32) * 2 + 1];
        #pragma unroll
        for (int o = 16; o > 0; o >>= 1) {
            d0 += __shfl_xor_sync(0xFFFFFFFFu, d0, o);
            d1 += __shfl_xor_sync(0xFFFFFFFFu, d1, o);
        }
        if (lane == 0) {
            d0 += sb2v[0]; d1 += sb2v[1];
            int fixed;
            if (mode == 0)      fixed = ((const int*)mask)[i] != 0;
            else if (mode == 1) fixed = ((const float*)mask)[i] != 0.f;
            else                fixed = ((const unsigned char*)mask)[i] != 0;
            if (fixed) { d0 = 0.f; d1 = 0.f; }
            out[i * 2]     = x[i * 6]     + d0;
            out[i * 2 + 1] = x[i * 6 + 1] + d1;
            if (out_size >= 4 * n) {
                out[2 * n + i * 2]     = d0;
                out[2 * n + i * 2 + 1] = d1;
            }
        }
        __syncwarp();
    }
}

// ---------------- launch ----------------
extern "C" void kernel_launch(void* const* d_in, const int* in_sizes, int n_in,
                              void* d_out, int out_size) {
    const float* x    = (const float*)d_in[0];
    const int*   ei   = (const int*)d_in[1];
    const float* ea   = (const float*)d_in[2];
    const float* tmp  = (const float*)d_in[3];
    const void*  mask = d_in[4];
    const float* encW = (const float*)d_in[5];
    const float* encB = (const float*)d_in[6];
    const float* encG = (const float*)d_in[7];
    const float* encBe= (const float*)d_in[8];
    const float* fW1  = (const float*)d_in[9];
    const float* fb1  = (const float*)d_in[10];
    const float* fW2  = (const float*)d_in[11];
    const float* fb2  = (const float*)d_in[12];
    const float* Wl   = (const float*)d_in[13];
    const float* bl   = (const float*)d_in[14];
    const float* Wr   = (const float*)d_in[15];
    const float* br   = (const float*)d_in[16];
    const float* We   = (const float*)d_in[17];
    const float* att  = (const float*)d_in[18];
    const float* cb   = (const float*)d_in[19];
    const float* lng  = (const float*)d_in[20];
    const float* lnb  = (const float*)d_in[21];
    const float* dW1  = (const float*)d_in[22];
    const float* db1  = (const float*)d_in[23];
    const float* dW2  = (const float*)d_in[24];
    const float* db2  = (const float*)d_in[25];
    float* out = (float*)d_out;

    int n = in_sizes[0] / 6;
    int e = in_sizes[2] / 4;

    const int gemm_smem = 256 * AST * 2;                // 69632
    const int prep_smem = (17536 + 2048) * 4;           // 78336
    cudaFuncSetAttribute(k_scan_prep, cudaFuncAttributeMaxDynamicSharedMemorySize, prep_smem);
    cudaFuncSetAttribute(k_gemm, cudaFuncAttributeMaxDynamicSharedMemorySize, gemm_smem);
    cudaFuncSetAttribute(k_scatter_gemm, cudaFuncAttributeMaxDynamicSharedMemorySize, gemm_smem);

    int gB = 2 * ((n + 127) / 128);     // 2 half-gemm blocks per 128-row tile
    int sB = (e + 1023) / 1024;

    __half* Wh = nullptr;
    cudaGetSymbolAddress((void**)&Wh, g_Wh);

    // launches: count(0), scan_prep(1), scatter_gemm0(2), node0(3) <- profiled
    k_count<<<(e + 255) / 256, 256>>>(ei, (const int*)mask, Wl, Wr, e, n);
    k_scan_prep<<<201, 1024, prep_smem>>>(x, tmp, encW, encB, encG, encBe,
                                          fW1, fb1, fW2, fb2, n);
    k_scatter_gemm<<<gB + sB, 512, gemm_smem>>>(Wh, bl, br,
                                                ei, (const float4*)ea, e, n, gB);
    k_node<<<(n + 7) / 8, 256>>>(We, att, cb, lng, lnb, n);

    for (int l = 1; l < 4; l++) {
        k_gemm<<<gB, 512, gemm_smem>>>(Wh + l * 32768, bl + l * 128,
                                       br + l * 128, n);
        k_node<<<(n + 7) / 8, 256>>>(We + l * 512, att + l * 128,
                                     cb + l * 128, lng + l * 128, lnb + l * 128, n);
    }

    k_dec<<<296, 256>>>(dW1, db1, dW2, db2, x, mask, out, n, out_size);
}